// round 1
// baseline (speedup 1.0000x reference)
#include <cuda_runtime.h>
#include <math.h>

#define B_   2
#define S_   2048
#define D_   1024
#define H_   16
#define DK_  64
#define M_TOT (B_*S_)          // 4096

#define TAB_N   4096
#define TAB_LO  (-8.0f)
#define TAB_INVH 256.0f        // TAB_N / (HI-LO)

// ---- scratch (device globals; no runtime allocation allowed) ----
__device__ float g_Q[B_*H_*S_*DK_];
__device__ float g_K[B_*H_*S_*DK_];
__device__ float g_V[B_*H_*S_*DK_];
__device__ float g_att[(size_t)M_TOT*D_];
__device__ float g_tab[TAB_N+1];

// =====================================================================
// 1) Build the fuzzy-membership lookup table: f(s) = sum_i exp(-(s-c)^2/2w^2) / (3*T)
// =====================================================================
__global__ void build_table(const float* __restrict__ centers,
                            const float* __restrict__ widths,
                            const float* __restrict__ temp) {
    int i = blockIdx.x * blockDim.x + threadIdx.x;
    if (i > TAB_N) return;
    float s = TAB_LO + (float)i * (1.0f / TAB_INVH);
    float acc = 0.0f;
    #pragma unroll 1
    for (int j = 0; j < H_*3; j++) {
        float c = centers[j];
        float w = widths[j];
        float d = s - c;
        acc += expf(-(d*d) / (2.0f * w * w));
    }
    g_tab[i] = acc / (3.0f * temp[0]);
}

// =====================================================================
// 2) GEMM:  C = A @ W^T + bias,  A[M,K] row-major, W[N,K] row-major.
//    MODE 0: flat store C[row*D_+col]
//    MODE 1: head-layout store into [(b*H+h)*S + s]*DK + dk  (for Q/K/V)
//    Tiling: 128x128x16, 256 threads, 8x8 per thread.
// =====================================================================
template<int MODE>
__global__ void __launch_bounds__(256)
gemm128(const float* __restrict__ A, const float* __restrict__ W,
        const float* __restrict__ bias, float* __restrict__ C, float outscale) {
    __shared__ float As[16][132];
    __shared__ float Bs[16][132];

    int tid = threadIdx.x;
    int tx = tid & 15, ty = tid >> 4;
    int m0 = blockIdx.y * 128;
    int n0 = blockIdx.x * 128;

    int lr = tid >> 2;            // 0..63
    int lc = (tid & 3) * 4;       // 0,4,8,12

    float acc[8][8];
    #pragma unroll
    for (int r = 0; r < 8; r++)
        #pragma unroll
        for (int c = 0; c < 8; c++) acc[r][c] = 0.0f;

    for (int k0 = 0; k0 < D_; k0 += 16) {
        float4 a0 = *(const float4*)(A + (size_t)(m0+lr)*D_    + k0 + lc);
        float4 a1 = *(const float4*)(A + (size_t)(m0+lr+64)*D_ + k0 + lc);
        float4 b0 = *(const float4*)(W + (size_t)(n0+lr)*D_    + k0 + lc);
        float4 b1 = *(const float4*)(W + (size_t)(n0+lr+64)*D_ + k0 + lc);
        __syncthreads();
        As[lc+0][lr]    = a0.x; As[lc+1][lr]    = a0.y; As[lc+2][lr]    = a0.z; As[lc+3][lr]    = a0.w;
        As[lc+0][lr+64] = a1.x; As[lc+1][lr+64] = a1.y; As[lc+2][lr+64] = a1.z; As[lc+3][lr+64] = a1.w;
        Bs[lc+0][lr]    = b0.x; Bs[lc+1][lr]    = b0.y; Bs[lc+2][lr]    = b0.z; Bs[lc+3][lr]    = b0.w;
        Bs[lc+0][lr+64] = b1.x; Bs[lc+1][lr+64] = b1.y; Bs[lc+2][lr+64] = b1.z; Bs[lc+3][lr+64] = b1.w;
        __syncthreads();

        #pragma unroll
        for (int k = 0; k < 16; k++) {
            float4 af0 = *(const float4*)&As[k][ty*8];
            float4 af1 = *(const float4*)&As[k][ty*8+4];
            float4 bf0 = *(const float4*)&Bs[k][tx*8];
            float4 bf1 = *(const float4*)&Bs[k][tx*8+4];
            float a_[8] = {af0.x, af0.y, af0.z, af0.w, af1.x, af1.y, af1.z, af1.w};
            float b_[8] = {bf0.x, bf0.y, bf0.z, bf0.w, bf1.x, bf1.y, bf1.z, bf1.w};
            #pragma unroll
            for (int r = 0; r < 8; r++)
                #pragma unroll
                for (int c = 0; c < 8; c++)
                    acc[r][c] += a_[r] * b_[c];
        }
    }

    // epilogue
    #pragma unroll
    for (int r = 0; r < 8; r++) {
        int row = m0 + ty*8 + r;
        #pragma unroll
        for (int cg = 0; cg < 8; cg += 4) {
            int col = n0 + tx*8 + cg;
            float4 bb = *(const float4*)(bias + col);
            float4 o;
            o.x = (acc[r][cg+0] + bb.x) * outscale;
            o.y = (acc[r][cg+1] + bb.y) * outscale;
            o.z = (acc[r][cg+2] + bb.z) * outscale;
            o.w = (acc[r][cg+3] + bb.w) * outscale;
            if (MODE == 0) {
                *(float4*)(C + (size_t)row*D_ + col) = o;
            } else {
                int b = row >> 11, s = row & 2047;
                int h = col >> 6, dk = col & 63;
                *(float4*)(C + ((size_t)((b*H_ + h)*S_ + s))*DK_ + dk) = o;
            }
        }
    }
}

// =====================================================================
// 3) Flash attention with fuzzy-table logits.
//    grid = (S/64 q-tiles, B*H);  256 threads (16x16), 4x4 per thread.
// =====================================================================
__global__ void __launch_bounds__(256)
attn_kernel(float* __restrict__ outp) {
    extern __shared__ float sm[];
    float* tab = sm;                       // 4104 floats (padded)
    float* Qts = tab + 4104;               // [64][68] transposed: Qts[d*68+i]
    float* Kts = Qts + 64*68;              // [64][68]
    float* Vt  = Kts + 64*68;              // [64][64] row-major
    float* Pts = Vt  + 64*64;              // [64][68] transposed: Pts[j*68+i]

    int tid = threadIdx.x;
    int tx = tid & 15, ty = tid >> 4;
    int bh = blockIdx.y;
    int q0 = blockIdx.x * 64;

    for (int i = tid; i <= TAB_N; i += 256) tab[i] = g_tab[i];

    const float* Qg = g_Q + ((size_t)bh * S_ + q0) * DK_;
    for (int idx = tid; idx < 4096; idx += 256) {
        int i = idx >> 6, d = idx & 63;
        Qts[d*68 + i] = Qg[idx];
    }

    float acc[4][4];
    float m[4], l[4];
    #pragma unroll
    for (int r = 0; r < 4; r++) {
        m[r] = -1e30f; l[r] = 0.0f;
        #pragma unroll
        for (int c = 0; c < 4; c++) acc[r][c] = 0.0f;
    }

    const float* Kbase = g_K + (size_t)bh * S_ * DK_;
    const float* Vbase = g_V + (size_t)bh * S_ * DK_;

    for (int kt = 0; kt < S_; kt += 64) {
        __syncthreads();   // prev-iter reads of Kts/Vt/Pts complete
        const float* Kg = Kbase + (size_t)kt * DK_;
        const float* Vg = Vbase + (size_t)kt * DK_;
        for (int idx = tid; idx < 4096; idx += 256) {
            int i = idx >> 6, d = idx & 63;
            Kts[d*68 + i] = Kg[idx];
        }
        for (int idx = tid; idx < 1024; idx += 256)
            ((float4*)Vt)[idx] = ((const float4*)Vg)[idx];
        __syncthreads();

        // ---- S = Q K^T (pre-scaled by 1/sqrt(dk) folded into Q) ----
        float sv[4][4];
        #pragma unroll
        for (int r = 0; r < 4; r++)
            #pragma unroll
            for (int c = 0; c < 4; c++) sv[r][c] = 0.0f;
        #pragma unroll 8
        for (int d = 0; d < 64; d++) {
            float4 qa = *(const float4*)(Qts + d*68 + ty*4);
            float4 kb = *(const float4*)(Kts + d*68 + tx*4);
            float qa_[4] = {qa.x, qa.y, qa.z, qa.w};
            float kb_[4] = {kb.x, kb.y, kb.z, kb.w};
            #pragma unroll
            for (int r = 0; r < 4; r++)
                #pragma unroll
                for (int c = 0; c < 4; c++)
                    sv[r][c] += qa_[r] * kb_[c];
        }

        // ---- fuzzy logits via table (lerp) ----
        #pragma unroll
        for (int r = 0; r < 4; r++)
            #pragma unroll
            for (int c = 0; c < 4; c++) {
                float t = (sv[r][c] - TAB_LO) * TAB_INVH;
                t = fminf(fmaxf(t, 0.0f), (float)(TAB_N - 1));
                int i0 = (int)t;
                float fr = t - (float)i0;
                float f0 = tab[i0];
                sv[r][c] = f0 + fr * (tab[i0+1] - f0);
            }

        // ---- online softmax update ----
        unsigned FULL = 0xffffffffu;
        #pragma unroll
        for (int r = 0; r < 4; r++) {
            float rmax = fmaxf(fmaxf(sv[r][0], sv[r][1]), fmaxf(sv[r][2], sv[r][3]));
            #pragma unroll
            for (int off = 1; off < 16; off <<= 1)
                rmax = fmaxf(rmax, __shfl_xor_sync(FULL, rmax, off));
            float mnew = fmaxf(m[r], rmax);
            float alpha = __expf(m[r] - mnew);
            float psum = 0.0f;
            #pragma unroll
            for (int c = 0; c < 4; c++) {
                float p = __expf(sv[r][c] - mnew);
                Pts[(tx*4 + c)*68 + ty*4 + r] = p;
                psum += p;
            }
            #pragma unroll
            for (int off = 1; off < 16; off <<= 1)
                psum += __shfl_xor_sync(FULL, psum, off);
            l[r] = l[r]*alpha + psum;
            m[r] = mnew;
            #pragma unroll
            for (int c = 0; c < 4; c++) acc[r][c] *= alpha;
        }
        __syncthreads();   // Pts visible to all

        // ---- acc += P V ----
        #pragma unroll 8
        for (int j = 0; j < 64; j++) {
            float4 pa = *(const float4*)(Pts + j*68 + ty*4);
            float4 vb = *(const float4*)(Vt  + j*64 + tx*4);
            float pa_[4] = {pa.x, pa.y, pa.z, pa.w};
            float vb_[4] = {vb.x, vb.y, vb.z, vb.w};
            #pragma unroll
            for (int r = 0; r < 4; r++)
                #pragma unroll
                for (int c = 0; c < 4; c++)
                    acc[r][c] += pa_[r] * vb_[c];
        }
    }

    // ---- write attended in [b, s, h, dk] flat ([M, D]) layout ----
    int b = bh >> 4, h = bh & 15;
    #pragma unroll
    for (int r = 0; r < 4; r++) {
        int s = q0 + ty*4 + r;
        float inv = 1.0f / l[r];
        float4 o = make_float4(acc[r][0]*inv, acc[r][1]*inv, acc[r][2]*inv, acc[r][3]*inv);
        *(float4*)(outp + ((size_t)(b*S_ + s))*D_ + h*64 + tx*4) = o;
    }
}

// =====================================================================
// launch
// =====================================================================
extern "C" void kernel_launch(void* const* d_in, const int* in_sizes, int n_in,
                              void* d_out, int out_size) {
    (void)in_sizes; (void)n_in; (void)out_size;
    const float* query   = (const float*)d_in[0];
    const float* key_in  = (const float*)d_in[1];
    const float* value   = (const float*)d_in[2];
    const float* w_q     = (const float*)d_in[3];
    const float* b_q     = (const float*)d_in[4];
    const float* w_k     = (const float*)d_in[5];
    const float* b_k     = (const float*)d_in[6];
    const float* w_v     = (const float*)d_in[7];
    const float* b_v     = (const float*)d_in[8];
    const float* w_o     = (const float*)d_in[9];
    const float* b_o     = (const float*)d_in[10];
    const float* centers = (const float*)d_in[11];
    const float* widths  = (const float*)d_in[12];
    const float* temp    = (const float*)d_in[13];
    float* out = (float*)d_out;

    float *pQ, *pK, *pV, *pAtt;
    cudaGetSymbolAddress((void**)&pQ,   g_Q);
    cudaGetSymbolAddress((void**)&pK,   g_K);
    cudaGetSymbolAddress((void**)&pV,   g_V);
    cudaGetSymbolAddress((void**)&pAtt, g_att);

    build_table<<<(TAB_N + 256)/256, 256>>>(centers, widths, temp);

    dim3 ggrid(D_/128, M_TOT/128);   // (8, 32)
    // fold 1/sqrt(DK)=0.125 into Q
    gemm128<1><<<ggrid, 256>>>(query,  w_q, b_q, pQ, 0.125f);
    gemm128<1><<<ggrid, 256>>>(key_in, w_k, b_k, pK, 1.0f);
    gemm128<1><<<ggrid, 256>>>(value,  w_v, b_v, pV, 1.0f);

    const int SMEM_BYTES = (4104 + 64*68 + 64*68 + 64*64 + 64*68) * 4;  // 85024
    cudaFuncSetAttribute(attn_kernel, cudaFuncAttributeMaxDynamicSharedMemorySize, SMEM_BYTES);
    attn_kernel<<<dim3(S_/64, B_*H_), 256, SMEM_BYTES>>>(pAtt);

    gemm128<0><<<ggrid, 256>>>(pAtt, w_o, b_o, out, 1.0f);
}

// round 6
// speedup vs baseline: 2.4854x; 2.4854x over previous
#include <cuda_runtime.h>
#include <cuda_bf16.h>
#include <cstdint>
#include <math.h>

typedef __nv_bfloat16 bf16;

#define B_   2
#define S_   2048
#define D_   1024
#define H_   16
#define DK_  64
#define M_TOT (B_*S_)          // 4096

#define TAB_N   4096
#define TAB_LO  (-8.0f)
#define TAB_INVH 256.0f

// ---- scratch (device globals) ----
__device__ float g_tab[TAB_N+1];
__device__ float g_att[(size_t)M_TOT*D_];
__device__ bf16 g_ahi[(size_t)M_TOT*D_];
__device__ bf16 g_alo[(size_t)M_TOT*D_];
__device__ bf16 g_whi[(size_t)D_*D_];
__device__ bf16 g_wlo[(size_t)D_*D_];
__device__ bf16 g_Qhi[B_*H_*S_*DK_];
__device__ bf16 g_Qlo[B_*H_*S_*DK_];
__device__ bf16 g_Khi[B_*H_*S_*DK_];
__device__ bf16 g_Klo[B_*H_*S_*DK_];
__device__ bf16 g_Vhi[B_*H_*S_*DK_];
__device__ bf16 g_Vlo[B_*H_*S_*DK_];

// =====================================================================
// PTX helpers (all target-independent: sm_80-class instructions)
// =====================================================================
__device__ __forceinline__ uint32_t smem_u32(const void* p) {
    uint32_t a;
    asm("{ .reg .u64 t; cvta.to.shared.u64 t, %1; cvt.u32.u64 %0, t; }" : "=r"(a) : "l"(p));
    return a;
}
#define CP_ASYNC16(dst, src) asm volatile("cp.async.ca.shared.global [%0], [%1], 16;" :: "r"(dst), "l"(src))
#define CP_COMMIT() asm volatile("cp.async.commit_group;" ::: "memory")
#define CP_WAIT(n)  asm volatile("cp.async.wait_group %0;" :: "n"(n) : "memory")

__device__ __forceinline__ void ldsm4(uint32_t* r, uint32_t a) {
    asm volatile("ldmatrix.sync.aligned.m8n8.x4.shared.b16 {%0,%1,%2,%3}, [%4];"
        : "=r"(r[0]),"=r"(r[1]),"=r"(r[2]),"=r"(r[3]) : "r"(a));
}
__device__ __forceinline__ void ldsm4t(uint32_t* r, uint32_t a) {
    asm volatile("ldmatrix.sync.aligned.m8n8.x4.trans.shared.b16 {%0,%1,%2,%3}, [%4];"
        : "=r"(r[0]),"=r"(r[1]),"=r"(r[2]),"=r"(r[3]) : "r"(a));
}
__device__ __forceinline__ void mma_bf16(float* d, const uint32_t* a, uint32_t b0, uint32_t b1) {
    asm volatile("mma.sync.aligned.m16n8k16.row.col.f32.bf16.bf16.f32 "
        "{%0,%1,%2,%3}, {%4,%5,%6,%7}, {%8,%9}, {%0,%1,%2,%3};"
        : "+f"(d[0]),"+f"(d[1]),"+f"(d[2]),"+f"(d[3])
        : "r"(a[0]),"r"(a[1]),"r"(a[2]),"r"(a[3]), "r"(b0),"r"(b1));
}
// ldmatrix per-thread address: 16 rows x 2 column-halves of 16B
__device__ __forceinline__ uint32_t ldsm_addr(uint32_t base, int lane, int strideB) {
    return base + (uint32_t)((lane & 15) * strideB + ((lane >> 4) << 4));
}
__device__ __forceinline__ uint32_t pack_hi(float a, float b, float& ra, float& rb) {
    __nv_bfloat162 h = __floats2bfloat162_rn(a, b);
    ra = a - __bfloat162float(h.x);
    rb = b - __bfloat162float(h.y);
    return *reinterpret_cast<uint32_t*>(&h);
}
__device__ __forceinline__ uint32_t pack2(float a, float b) {
    __nv_bfloat162 h = __floats2bfloat162_rn(a, b);
    return *reinterpret_cast<uint32_t*>(&h);
}

// =====================================================================
// 0) fp32 -> bf16 hi/lo split
// =====================================================================
__global__ void split_bf16(const float* __restrict__ in,
                           bf16* __restrict__ hi, bf16* __restrict__ lo, int n4) {
    int i = blockIdx.x * blockDim.x + threadIdx.x;
    if (i >= n4) return;
    float4 v = ((const float4*)in)[i];
    float r0,r1,r2,r3;
    uint32_t h0 = pack_hi(v.x, v.y, r0, r1);
    uint32_t h1 = pack_hi(v.z, v.w, r2, r3);
    uint2 ph = make_uint2(h0, h1);
    uint2 pl = make_uint2(pack2(r0, r1), pack2(r2, r3));
    *(uint2*)(hi + 4*(size_t)i) = ph;
    *(uint2*)(lo + 4*(size_t)i) = pl;
}

// =====================================================================
// 1) table: g(s) = exp( sum_i gauss_i(s) / (3 T) )   -- exp folded in!
// =====================================================================
__global__ void build_table(const float* __restrict__ centers,
                            const float* __restrict__ widths,
                            const float* __restrict__ temp) {
    int i = blockIdx.x * blockDim.x + threadIdx.x;
    if (i > TAB_N) return;
    float s = TAB_LO + (float)i * (1.0f / TAB_INVH);
    float acc = 0.0f;
    #pragma unroll 1
    for (int j = 0; j < H_*3; j++) {
        float c = centers[j];
        float w = widths[j];
        float d = s - c;
        acc += expf(-(d*d) / (2.0f * w * w));
    }
    g_tab[i] = expf(acc / (3.0f * temp[0]));
}

// =====================================================================
// 2) HMMA GEMM: C = A@W^T + bias, bf16 hi/lo split (3 MMA products).
//    128x128 tile, k-chunk 32, 8 warps (4m x 2n), cp.async double buffer.
//    MODE 0: fp32 flat store. MODE 1: bf16 hi/lo head-layout store.
// =====================================================================
#define GK 32
#define GSTRIDE 80           // bytes per smem row (32+8 bf16)
#define GBUF 10240           // one array: 128 rows * 80B
#define GEMM_SMEM (2*4*GBUF) // 81920

template<int MODE>
__global__ void __launch_bounds__(256)
gemm_mma(const bf16* __restrict__ Agh, const bf16* __restrict__ Agl,
         const bf16* __restrict__ Wgh, const bf16* __restrict__ Wgl,
         const float* __restrict__ bias, float scale,
         float* __restrict__ C, bf16* __restrict__ Chi, bf16* __restrict__ Clo) {
    extern __shared__ char smem[];
    const uint32_t sb = smem_u32(smem);
    const int tid = threadIdx.x, w = tid >> 5, lane = tid & 31;
    const int m0 = blockIdx.y * 128, n0 = blockIdx.x * 128;
    const int wm = (w >> 1) * 32, wn = (w & 1) * 64;

    float acc[2][8][4];
    #pragma unroll
    for (int a = 0; a < 2; a++)
        #pragma unroll
        for (int b = 0; b < 8; b++)
            #pragma unroll
            for (int c = 0; c < 4; c++) acc[a][b][c] = 0.0f;

    auto loadChunk = [&](int c, int buf) {
        const uint32_t off = sb + buf * 4 * GBUF;
        const int k0 = c * GK;
        #pragma unroll
        for (int i = 0; i < 8; i++) {
            int u = tid + i * 256;
            int arr = u >> 9, idx = u & 511;
            int r = idx >> 2, cc = idx & 3;
            const bf16* src;
            if      (arr == 0) src = Agh + (size_t)(m0 + r) * D_ + k0 + cc * 8;
            else if (arr == 1) src = Agl + (size_t)(m0 + r) * D_ + k0 + cc * 8;
            else if (arr == 2) src = Wgh + (size_t)(n0 + r) * D_ + k0 + cc * 8;
            else               src = Wgl + (size_t)(n0 + r) * D_ + k0 + cc * 8;
            CP_ASYNC16(off + arr * GBUF + r * GSTRIDE + cc * 16, src);
        }
    };
    auto compute = [&](int buf) {
        const uint32_t off = sb + buf * 4 * GBUF;
        uint32_t Ah[2][2][4], Al[2][2][4];
        #pragma unroll
        for (int mi = 0; mi < 2; mi++)
            #pragma unroll
            for (int kf = 0; kf < 2; kf++) {
                uint32_t base = off + (wm + mi * 16) * GSTRIDE + kf * 32;
                ldsm4(Ah[mi][kf], ldsm_addr(base, lane, GSTRIDE));
                ldsm4(Al[mi][kf], ldsm_addr(base + GBUF, lane, GSTRIDE));
            }
        #pragma unroll
        for (int kf = 0; kf < 2; kf++) {
            uint32_t Bh[4][4], Bl[4][4];
            #pragma unroll
            for (int nt = 0; nt < 4; nt++) {
                uint32_t base = off + 2 * GBUF + (wn + nt * 16) * GSTRIDE + kf * 32;
                ldsm4(Bh[nt], ldsm_addr(base, lane, GSTRIDE));
                ldsm4(Bl[nt], ldsm_addr(base + GBUF, lane, GSTRIDE));
            }
            #pragma unroll
            for (int pr = 0; pr < 3; pr++)
                #pragma unroll
                for (int mi = 0; mi < 2; mi++)
                    #pragma unroll
                    for (int nt = 0; nt < 4; nt++) {
                        const uint32_t* A  = (pr == 2) ? Al[mi][kf] : Ah[mi][kf];
                        const uint32_t* Bq = (pr == 1) ? Bl[nt] : Bh[nt];
                        mma_bf16(acc[mi][2*nt],   A, Bq[0], Bq[2]);
                        mma_bf16(acc[mi][2*nt+1], A, Bq[1], Bq[3]);
                    }
        }
    };

    loadChunk(0, 0); CP_COMMIT();
    for (int c = 0; c < 32; c++) {
        if (c < 31) { loadChunk(c + 1, (c + 1) & 1); CP_COMMIT(); CP_WAIT(1); }
        else        { CP_WAIT(0); }
        __syncthreads();
        compute(c & 1);
        __syncthreads();
    }

    // epilogue
    #pragma unroll
    for (int mi = 0; mi < 2; mi++) {
        int r0 = m0 + wm + mi * 16 + (lane >> 2);
        #pragma unroll
        for (int ni = 0; ni < 8; ni++) {
            int col = n0 + wn + ni * 8 + 2 * (lane & 3);
            float b0v = __ldg(bias + col), b1v = __ldg(bias + col + 1);
            #pragma unroll
            for (int rr = 0; rr < 2; rr++) {
                int row = r0 + rr * 8;
                float v0 = (acc[mi][ni][2*rr]   + b0v) * scale;
                float v1 = (acc[mi][ni][2*rr+1] + b1v) * scale;
                if (MODE == 0) {
                    float2 o = make_float2(v0, v1);
                    *(float2*)(C + (size_t)row * D_ + col) = o;
                } else {
                    int bb = row >> 11, s = row & 2047, h = col >> 6, dk = col & 63;
                    size_t p = ((size_t)((bb * H_ + h) * S_ + s)) * DK_ + dk;
                    float ra, rb;
                    uint32_t hi2 = pack_hi(v0, v1, ra, rb);
                    *(uint32_t*)(Chi + p) = hi2;
                    *(uint32_t*)(Clo + p) = pack2(ra, rb);
                }
            }
        }
    }
}

// =====================================================================
// 3) HMMA flash attention (no online max; exp folded into table).
//    Block: 256 thr (8 warps), q-tile 128, k-tile 64. Warp = 16 q-rows.
//    smem: Khi@0 Klo@9216 Vhi@18432 Vlo@27648 (row stride 144B), table float2 @36864
// =====================================================================
#define AT_SMEM (36864 + (TAB_N)*8)

__global__ void __launch_bounds__(256)
attn_mma(const bf16* __restrict__ Qh, const bf16* __restrict__ Ql,
         const bf16* __restrict__ Kh, const bf16* __restrict__ Kl,
         const bf16* __restrict__ Vh, const bf16* __restrict__ Vl,
         float* __restrict__ outp) {
    extern __shared__ char smem[];
    const uint32_t sb = smem_u32(smem);
    float2* tabp = (float2*)(smem + 36864);
    const int tid = threadIdx.x, w = tid >> 5, lane = tid & 31;
    const int bh = blockIdx.y, q0 = blockIdx.x * 128;
    const size_t hb = (size_t)bh * S_ * DK_;

    for (int i = tid; i < TAB_N; i += 256) {
        float a = g_tab[i];
        tabp[i] = make_float2(a, g_tab[i + 1] - a);
    }

    // ---- stage Q hi/lo, load fragments (4 k16 frags per precision) ----
    uint32_t qh[4][4], ql[4][4];
    for (int u = tid; u < 1024; u += 256) {
        int r = u >> 3, c = u & 7;
        *(uint4*)(smem + r * 144 + c * 16) = *(const uint4*)(Qh + hb + (size_t)(q0 + r) * DK_ + c * 8);
    }
    __syncthreads();
    #pragma unroll
    for (int kf = 0; kf < 4; kf++)
        ldsm4(qh[kf], ldsm_addr(sb + (w * 16) * 144 + kf * 32, lane, 144));
    __syncthreads();
    for (int u = tid; u < 1024; u += 256) {
        int r = u >> 3, c = u & 7;
        *(uint4*)(smem + r * 144 + c * 16) = *(const uint4*)(Ql + hb + (size_t)(q0 + r) * DK_ + c * 8);
    }
    __syncthreads();
    #pragma unroll
    for (int kf = 0; kf < 4; kf++)
        ldsm4(ql[kf], ldsm_addr(sb + (w * 16) * 144 + kf * 32, lane, 144));

    float acc[8][4];
    #pragma unroll
    for (int j = 0; j < 8; j++)
        #pragma unroll
        for (int e = 0; e < 4; e++) acc[j][e] = 0.0f;
    float ls0 = 0.0f, ls1 = 0.0f;

    for (int kt = 0; kt < S_; kt += 64) {
        __syncthreads();   // all warps done reading tiles (or Q frags) of prev iter
        for (int i = 0; i < 8; i++) {
            int u = tid + i * 256;
            int arr = u >> 9, idx = u & 511, r = idx >> 3, c = idx & 7;
            const bf16* src = (arr == 0 ? Kh : arr == 1 ? Kl : arr == 2 ? Vh : Vl)
                              + hb + (size_t)(kt + r) * DK_ + c * 8;
            CP_ASYNC16(sb + arr * 9216 + r * 144 + c * 16, src);
        }
        CP_COMMIT(); CP_WAIT(0);
        __syncthreads();

        // ---- S = Q K^T (keys = n) ----
        float sc[8][4];
        #pragma unroll
        for (int j = 0; j < 8; j++)
            #pragma unroll
            for (int e = 0; e < 4; e++) sc[j][e] = 0.0f;
        #pragma unroll
        for (int kf = 0; kf < 4; kf++) {
            uint32_t kb[4][4], kl2[4][4];
            #pragma unroll
            for (int nt = 0; nt < 4; nt++) {
                uint32_t base = sb + (nt * 16) * 144 + kf * 32;
                ldsm4(kb[nt],  ldsm_addr(base, lane, 144));
                ldsm4(kl2[nt], ldsm_addr(base + 9216, lane, 144));
            }
            #pragma unroll
            for (int pr = 0; pr < 3; pr++)
                #pragma unroll
                for (int nt = 0; nt < 4; nt++) {
                    const uint32_t* A  = (pr == 2) ? ql[kf] : qh[kf];
                    const uint32_t* Bq = (pr == 1) ? kl2[nt] : kb[nt];
                    mma_bf16(sc[2*nt],   A, Bq[0], Bq[2]);
                    mma_bf16(sc[2*nt+1], A, Bq[1], Bq[3]);
                }
        }

        // ---- p = table(s) via lerp (NO exp), accumulate row sums ----
        #pragma unroll
        for (int j = 0; j < 8; j++) {
            #pragma unroll
            for (int e = 0; e < 4; e++) {
                float t = (sc[j][e] - TAB_LO) * TAB_INVH;
                t = fminf(fmaxf(t, 0.0f), 4095.0f);
                int i0 = (int)t;
                float fr = t - (float)i0;
                float2 tv = tabp[i0];
                sc[j][e] = fmaf(fr, tv.y, tv.x);
            }
            ls0 += sc[j][0] + sc[j][1];
            ls1 += sc[j][2] + sc[j][3];
        }

        // ---- re-pipe P (C-frags -> A-frags), hi/lo split ----
        uint32_t ph[4][4], pl[4][4];
        #pragma unroll
        for (int kf = 0; kf < 4; kf++) {
            int j0 = 2 * kf;
            float r0a, r0b, r1a, r1b, r2a, r2b, r3a, r3b;
            ph[kf][0] = pack_hi(sc[j0][0],   sc[j0][1],   r0a, r0b);
            ph[kf][1] = pack_hi(sc[j0][2],   sc[j0][3],   r1a, r1b);
            ph[kf][2] = pack_hi(sc[j0+1][0], sc[j0+1][1], r2a, r2b);
            ph[kf][3] = pack_hi(sc[j0+1][2], sc[j0+1][3], r3a, r3b);
            pl[kf][0] = pack2(r0a, r0b);
            pl[kf][1] = pack2(r1a, r1b);
            pl[kf][2] = pack2(r2a, r2b);
            pl[kf][3] = pack2(r3a, r3b);
        }

        // ---- acc += P V  (keys = k via ldmatrix.trans on V[key][dk]) ----
        #pragma unroll
        for (int kf = 0; kf < 4; kf++) {
            uint32_t vb[4][4], vl2[4][4];
            #pragma unroll
            for (int dt = 0; dt < 4; dt++) {
                uint32_t base = sb + 18432 + (kf * 16) * 144 + dt * 32;
                ldsm4t(vb[dt],  ldsm_addr(base, lane, 144));
                ldsm4t(vl2[dt], ldsm_addr(base + 9216, lane, 144));
            }
            #pragma unroll
            for (int pr = 0; pr < 3; pr++)
                #pragma unroll
                for (int dt = 0; dt < 4; dt++) {
                    const uint32_t* A  = (pr == 2) ? pl[kf] : ph[kf];
                    const uint32_t* Bq = (pr == 1) ? vl2[dt] : vb[dt];
                    mma_bf16(acc[2*dt],   A, Bq[0], Bq[1]);
                    mma_bf16(acc[2*dt+1], A, Bq[2], Bq[3]);
                }
        }
    }

    // ---- normalize and write [b,s,h,dk] flat ----
    ls0 += __shfl_xor_sync(0xffffffffu, ls0, 1);
    ls0 += __shfl_xor_sync(0xffffffffu, ls0, 2);
    ls1 += __shfl_xor_sync(0xffffffffu, ls1, 1);
    ls1 += __shfl_xor_sync(0xffffffffu, ls1, 2);
    float inv0 = 1.0f / ls0, inv1 = 1.0f / ls1;
    int r0 = q0 + w * 16 + (lane >> 2);
    int bb = bh >> 4, h = bh & 15;
    #pragma unroll
    for (int j = 0; j < 8; j++) {
        int dk = j * 8 + 2 * (lane & 3);
        float2 o0 = make_float2(acc[j][0] * inv0, acc[j][1] * inv0);
        float2 o1 = make_float2(acc[j][2] * inv1, acc[j][3] * inv1);
        *(float2*)(outp + ((size_t)(bb * S_ + r0)) * D_ + h * 64 + dk) = o0;
        *(float2*)(outp + ((size_t)(bb * S_ + r0 + 8)) * D_ + h * 64 + dk) = o1;
    }
}

// =====================================================================
// launch
// =====================================================================
extern "C" void kernel_launch(void* const* d_in, const int* in_sizes, int n_in,
                              void* d_out, int out_size) {
    (void)in_sizes; (void)n_in; (void)out_size;
    const float* query   = (const float*)d_in[0];
    const float* key_in  = (const float*)d_in[1];
    const float* value   = (const float*)d_in[2];
    const float* w_q     = (const float*)d_in[3];
    const float* b_q     = (const float*)d_in[4];
    const float* w_k     = (const float*)d_in[5];
    const float* b_k     = (const float*)d_in[6];
    const float* w_v     = (const float*)d_in[7];
    const float* b_v     = (const float*)d_in[8];
    const float* w_o     = (const float*)d_in[9];
    const float* b_o     = (const float*)d_in[10];
    const float* centers = (const float*)d_in[11];
    const float* widths  = (const float*)d_in[12];
    const float* temp    = (const float*)d_in[13];
    float* out = (float*)d_out;

    float *pAtt;
    bf16 *pAhi, *pAlo, *pWhi, *pWlo;
    bf16 *pQhi, *pQlo, *pKhi, *pKlo, *pVhi, *pVlo;
    cudaGetSymbolAddress((void**)&pAtt, g_att);
    cudaGetSymbolAddress((void**)&pAhi, g_ahi);
    cudaGetSymbolAddress((void**)&pAlo, g_alo);
    cudaGetSymbolAddress((void**)&pWhi, g_whi);
    cudaGetSymbolAddress((void**)&pWlo, g_wlo);
    cudaGetSymbolAddress((void**)&pQhi, g_Qhi);
    cudaGetSymbolAddress((void**)&pQlo, g_Qlo);
    cudaGetSymbolAddress((void**)&pKhi, g_Khi);
    cudaGetSymbolAddress((void**)&pKlo, g_Klo);
    cudaGetSymbolAddress((void**)&pVhi, g_Vhi);
    cudaGetSymbolAddress((void**)&pVlo, g_Vlo);

    cudaFuncSetAttribute(gemm_mma<0>, cudaFuncAttributeMaxDynamicSharedMemorySize, GEMM_SMEM);
    cudaFuncSetAttribute(gemm_mma<1>, cudaFuncAttributeMaxDynamicSharedMemorySize, GEMM_SMEM);
    cudaFuncSetAttribute(attn_mma, cudaFuncAttributeMaxDynamicSharedMemorySize, AT_SMEM);

    const int NA4 = M_TOT * D_ / 4;
    const int NW4 = D_ * D_ / 4;
    dim3 ggrid(D_ / 128, M_TOT / 128);   // (8, 32)

    build_table<<<(TAB_N + 256) / 256, 256>>>(centers, widths, temp);

    // Q projection (fold 1/sqrt(DK) = 0.125)
    split_bf16<<<NA4 / 256, 256>>>(query, pAhi, pAlo, NA4);
    split_bf16<<<NW4 / 256, 256>>>(w_q, pWhi, pWlo, NW4);
    gemm_mma<1><<<ggrid, 256, GEMM_SMEM>>>(pAhi, pAlo, pWhi, pWlo, b_q, 0.125f,
                                           nullptr, pQhi, pQlo);
    // K projection
    split_bf16<<<NA4 / 256, 256>>>(key_in, pAhi, pAlo, NA4);
    split_bf16<<<NW4 / 256, 256>>>(w_k, pWhi, pWlo, NW4);
    gemm_mma<1><<<ggrid, 256, GEMM_SMEM>>>(pAhi, pAlo, pWhi, pWlo, b_k, 1.0f,
                                           nullptr, pKhi, pKlo);
    // V projection
    split_bf16<<<NA4 / 256, 256>>>(value, pAhi, pAlo, NA4);
    split_bf16<<<NW4 / 256, 256>>>(w_v, pWhi, pWlo, NW4);
    gemm_mma<1><<<ggrid, 256, GEMM_SMEM>>>(pAhi, pAlo, pWhi, pWlo, b_v, 1.0f,
                                           nullptr, pVhi, pVlo);

    // attention
    attn_mma<<<dim3(S_ / 128, B_ * H_), 256, AT_SMEM>>>(pQhi, pQlo, pKhi, pKlo,
                                                        pVhi, pVlo, pAtt);

    // output projection
    split_bf16<<<NA4 / 256, 256>>>(pAtt, pAhi, pAlo, NA4);
    split_bf16<<<NW4 / 256, 256>>>(w_o, pWhi, pWlo, NW4);
    gemm_mma<0><<<ggrid, 256, GEMM_SMEM>>>(pAhi, pAlo, pWhi, pWlo, b_o, 1.0f,
                                           out, nullptr, nullptr);
}

// round 11
// speedup vs baseline: 2.7117x; 1.0911x over previous
#include <cuda_runtime.h>
#include <cuda_bf16.h>
#include <cstdint>
#include <math.h>

typedef __nv_bfloat16 bf16;

#define B_   2
#define S_   2048
#define D_   1024
#define H_   16
#define DK_  64
#define M_TOT (B_*S_)          // 4096

#define TAB_N   4096
#define TAB_LO  (-8.0f)
#define TAB_INVH 256.0f

// ---- scratch (device globals) ----
__device__ float g_tab[TAB_N+1];
__device__ bf16 g_i3hi[3][(size_t)M_TOT*D_];   // split inputs: q, k, v
__device__ bf16 g_i3lo[3][(size_t)M_TOT*D_];
__device__ bf16 g_w4hi[4][(size_t)D_*D_];      // split weights: wq, wk, wv, wo
__device__ bf16 g_w4lo[4][(size_t)D_*D_];
__device__ bf16 g_ahi[(size_t)M_TOT*D_];       // attention output hi/lo
__device__ bf16 g_alo[(size_t)M_TOT*D_];
__device__ bf16 g_Qhi[B_*H_*S_*DK_];
__device__ bf16 g_Qlo[B_*H_*S_*DK_];
__device__ bf16 g_Khi[B_*H_*S_*DK_];
__device__ bf16 g_Klo[B_*H_*S_*DK_];
__device__ bf16 g_Vhi[B_*H_*S_*DK_];
__device__ bf16 g_Vlo[B_*H_*S_*DK_];

// =====================================================================
// PTX helpers (target-independent sm_80-class instructions)
// =====================================================================
__device__ __forceinline__ uint32_t smem_u32(const void* p) {
    uint32_t a;
    asm("{ .reg .u64 t; cvta.to.shared.u64 t, %1; cvt.u32.u64 %0, t; }" : "=r"(a) : "l"(p));
    return a;
}
#define CP_ASYNC16(dst, src) asm volatile("cp.async.ca.shared.global [%0], [%1], 16;" :: "r"(dst), "l"(src))
#define CP_COMMIT() asm volatile("cp.async.commit_group;" ::: "memory")
#define CP_WAIT(n)  asm volatile("cp.async.wait_group %0;" :: "n"(n) : "memory")

__device__ __forceinline__ void ldsm4(uint32_t* r, uint32_t a) {
    asm volatile("ldmatrix.sync.aligned.m8n8.x4.shared.b16 {%0,%1,%2,%3}, [%4];"
        : "=r"(r[0]),"=r"(r[1]),"=r"(r[2]),"=r"(r[3]) : "r"(a));
}
__device__ __forceinline__ void ldsm4t(uint32_t* r, uint32_t a) {
    asm volatile("ldmatrix.sync.aligned.m8n8.x4.trans.shared.b16 {%0,%1,%2,%3}, [%4];"
        : "=r"(r[0]),"=r"(r[1]),"=r"(r[2]),"=r"(r[3]) : "r"(a));
}
__device__ __forceinline__ void mma_bf16(float* d, const uint32_t* a, uint32_t b0, uint32_t b1) {
    asm volatile("mma.sync.aligned.m16n8k16.row.col.f32.bf16.bf16.f32 "
        "{%0,%1,%2,%3}, {%4,%5,%6,%7}, {%8,%9}, {%0,%1,%2,%3};"
        : "+f"(d[0]),"+f"(d[1]),"+f"(d[2]),"+f"(d[3])
        : "r"(a[0]),"r"(a[1]),"r"(a[2]),"r"(a[3]), "r"(b0),"r"(b1));
}
__device__ __forceinline__ uint32_t ldsm_addr(uint32_t base, int lane, int strideB) {
    return base + (uint32_t)((lane & 15) * strideB + ((lane >> 4) << 4));
}
__device__ __forceinline__ uint32_t pack_hi(float a, float b, float& ra, float& rb) {
    __nv_bfloat162 h = __floats2bfloat162_rn(a, b);
    ra = a - __bfloat162float(h.x);
    rb = b - __bfloat162float(h.y);
    return *reinterpret_cast<uint32_t*>(&h);
}
__device__ __forceinline__ uint32_t pack2(float a, float b) {
    __nv_bfloat162 h = __floats2bfloat162_rn(a, b);
    return *reinterpret_cast<uint32_t*>(&h);
}

// =====================================================================
// 0) batched fp32 -> bf16 hi/lo split for all 3 inputs + 4 weights
// =====================================================================
#define NIN4 (M_TOT*D_/4)   // 1048576
#define NWW4 (D_*D_/4)      // 262144

__global__ void split_all(const float* __restrict__ q, const float* __restrict__ k,
                          const float* __restrict__ v, const float* __restrict__ wq,
                          const float* __restrict__ wk, const float* __restrict__ wv,
                          const float* __restrict__ wo) {
    int i = blockIdx.x * blockDim.x + threadIdx.x;
    const float* src; bf16* hi; bf16* lo; size_t off;
    if (i < 3 * NIN4) {
        int seg = i / NIN4; off = (size_t)(i - seg * NIN4);
        src = seg == 0 ? q : seg == 1 ? k : v;
        hi = g_i3hi[seg]; lo = g_i3lo[seg];
    } else {
        int j = i - 3 * NIN4;
        if (j >= 4 * NWW4) return;
        int seg = j / NWW4; off = (size_t)(j - seg * NWW4);
        src = seg == 0 ? wq : seg == 1 ? wk : seg == 2 ? wv : wo;
        hi = g_w4hi[seg]; lo = g_w4lo[seg];
    }
    float4 vv = ((const float4*)src)[off];
    float r0, r1, r2, r3;
    uint32_t h0 = pack_hi(vv.x, vv.y, r0, r1);
    uint32_t h1 = pack_hi(vv.z, vv.w, r2, r3);
    *(uint2*)(hi + 4 * off) = make_uint2(h0, h1);
    *(uint2*)(lo + 4 * off) = make_uint2(pack2(r0, r1), pack2(r2, r3));
}

// =====================================================================
// 1) table: g(s) = exp( sum_i gauss_i(s) / (3 T) )
// =====================================================================
__global__ void build_table(const float* __restrict__ centers,
                            const float* __restrict__ widths,
                            const float* __restrict__ temp) {
    int i = blockIdx.x * blockDim.x + threadIdx.x;
    if (i > TAB_N) return;
    float s = TAB_LO + (float)i * (1.0f / TAB_INVH);
    float acc = 0.0f;
    #pragma unroll 1
    for (int j = 0; j < H_*3; j++) {
        float c = centers[j];
        float w = widths[j];
        float d = s - c;
        acc += expf(-(d*d) / (2.0f * w * w));
    }
    g_tab[i] = expf(acc / (3.0f * temp[0]));
}

// =====================================================================
// 2) HMMA GEMM, 2-stage cp.async pipeline, ONE sync per k-chunk.
//    128x128 tile, k-chunk 32, 8 warps (4m x 2n), hi/lo split (3 MMAs).
// =====================================================================
#define GK 32
#define GSTRIDE 80              // bytes per smem row (32+8 bf16)
#define GBUF 10240              // one array: 128 rows * 80B
#define GSTAGE (4*GBUF)         // 40960
#define GEMM_SMEM (2*GSTAGE)    // 81920

template<int MODE>
__global__ void __launch_bounds__(256)
gemm_mma(const bf16* __restrict__ Agh, const bf16* __restrict__ Agl,
         const bf16* __restrict__ Wgh, const bf16* __restrict__ Wgl,
         const float* __restrict__ bias, float scale,
         float* __restrict__ C, bf16* __restrict__ Chi, bf16* __restrict__ Clo) {
    extern __shared__ char smem[];
    const uint32_t sb = smem_u32(smem);
    const int tid = threadIdx.x, w = tid >> 5, lane = tid & 31;
    const int m0 = blockIdx.y * 128, n0 = blockIdx.x * 128;
    const int wm = (w >> 1) * 32, wn = (w & 1) * 64;

    float acc[2][8][4];
    #pragma unroll
    for (int a = 0; a < 2; a++)
        #pragma unroll
        for (int b = 0; b < 8; b++)
            #pragma unroll
            for (int c = 0; c < 4; c++) acc[a][b][c] = 0.0f;

    auto loadChunk = [&](int c, int buf) {
        const uint32_t off = sb + buf * GSTAGE;
        const int k0 = c * GK;
        #pragma unroll
        for (int i = 0; i < 8; i++) {
            int u = tid + i * 256;
            int arr = u >> 9, idx = u & 511;
            int r = idx >> 2, cc = idx & 3;
            const bf16* src;
            if      (arr == 0) src = Agh + (size_t)(m0 + r) * D_ + k0 + cc * 8;
            else if (arr == 1) src = Agl + (size_t)(m0 + r) * D_ + k0 + cc * 8;
            else if (arr == 2) src = Wgh + (size_t)(n0 + r) * D_ + k0 + cc * 8;
            else               src = Wgl + (size_t)(n0 + r) * D_ + k0 + cc * 8;
            CP_ASYNC16(off + arr * GBUF + r * GSTRIDE + cc * 16, src);
        }
    };
    auto compute = [&](int buf) {
        const uint32_t off = sb + buf * GSTAGE;
        uint32_t Ah[2][2][4], Al[2][2][4];
        #pragma unroll
        for (int mi = 0; mi < 2; mi++)
            #pragma unroll
            for (int kf = 0; kf < 2; kf++) {
                uint32_t base = off + (wm + mi * 16) * GSTRIDE + kf * 32;
                ldsm4(Ah[mi][kf], ldsm_addr(base, lane, GSTRIDE));
                ldsm4(Al[mi][kf], ldsm_addr(base + GBUF, lane, GSTRIDE));
            }
        #pragma unroll
        for (int kf = 0; kf < 2; kf++) {
            uint32_t Bh[4][4], Bl[4][4];
            #pragma unroll
            for (int nt = 0; nt < 4; nt++) {
                uint32_t base = off + 2 * GBUF + (wn + nt * 16) * GSTRIDE + kf * 32;
                ldsm4(Bh[nt], ldsm_addr(base, lane, GSTRIDE));
                ldsm4(Bl[nt], ldsm_addr(base + GBUF, lane, GSTRIDE));
            }
            #pragma unroll
            for (int pr = 0; pr < 3; pr++)
                #pragma unroll
                for (int mi = 0; mi < 2; mi++)
                    #pragma unroll
                    for (int nt = 0; nt < 4; nt++) {
                        const uint32_t* A  = (pr == 2) ? Al[mi][kf] : Ah[mi][kf];
                        const uint32_t* Bq = (pr == 1) ? Bl[nt] : Bh[nt];
                        mma_bf16(acc[mi][2*nt],   A, Bq[0], Bq[2]);
                        mma_bf16(acc[mi][2*nt+1], A, Bq[1], Bq[3]);
                    }
        }
    };

    loadChunk(0, 0); CP_COMMIT();
    for (int c = 0; c < 32; c++) {
        CP_WAIT(0);            // chunk c resident in buffer c&1
        __syncthreads();       // also releases buffer (c+1)&1 (computed at c-1)
        if (c + 1 < 32) { loadChunk(c + 1, (c + 1) & 1); CP_COMMIT(); }
        compute(c & 1);        // overlaps with in-flight load of chunk c+1
    }

    // epilogue
    #pragma unroll
    for (int mi = 0; mi < 2; mi++) {
        int r0 = m0 + wm + mi * 16 + (lane >> 2);
        #pragma unroll
        for (int ni = 0; ni < 8; ni++) {
            int col = n0 + wn + ni * 8 + 2 * (lane & 3);
            float b0v = __ldg(bias + col), b1v = __ldg(bias + col + 1);
            #pragma unroll
            for (int rr = 0; rr < 2; rr++) {
                int row = r0 + rr * 8;
                float v0 = (acc[mi][ni][2*rr]   + b0v) * scale;
                float v1 = (acc[mi][ni][2*rr+1] + b1v) * scale;
                if (MODE == 0) {
                    *(float2*)(C + (size_t)row * D_ + col) = make_float2(v0, v1);
                } else {
                    int bb = row >> 11, s = row & 2047, h = col >> 6, dk = col & 63;
                    size_t p = ((size_t)((bb * H_ + h) * S_ + s)) * DK_ + dk;
                    float ra, rb;
                    uint32_t hi2 = pack_hi(v0, v1, ra, rb);
                    *(uint32_t*)(Chi + p) = hi2;
                    *(uint32_t*)(Clo + p) = pack2(ra, rb);
                }
            }
        }
    }
}

// =====================================================================
// 3) HMMA flash attention, 2-stage pipelined K/V tiles, 1 sync/iter.
//    q-tile 128 (8 warps x 16 rows), k-tile 64. Writes bf16 hi/lo out.
//    stage buf: Khi@0 Klo@9216 Vhi@18432 Vlo@27648 (64 rows x 144B)
//    Q staged through buffer 0 before the pipeline; table after buffers.
// =====================================================================
#define ASTAGE 36864
#define AT_SMEM (2*ASTAGE + TAB_N*8)   // 73728 + 32768 = 106496

__global__ void __launch_bounds__(256)
attn_mma(const bf16* __restrict__ Qh, const bf16* __restrict__ Ql,
         const bf16* __restrict__ Kh, const bf16* __restrict__ Kl,
         const bf16* __restrict__ Vh, const bf16* __restrict__ Vl,
         bf16* __restrict__ Ohi, bf16* __restrict__ Olo) {
    extern __shared__ char smem[];
    const uint32_t sb = smem_u32(smem);
    float2* tabp = (float2*)(smem + 2 * ASTAGE);
    const int tid = threadIdx.x, w = tid >> 5, lane = tid & 31;
    const int bh = blockIdx.y, q0 = blockIdx.x * 128;
    const size_t hb = (size_t)bh * S_ * DK_;

    for (int i = tid; i < TAB_N; i += 256) {
        float a = g_tab[i];
        tabp[i] = make_float2(a, g_tab[i + 1] - a);
    }

    // ---- stage Q hi/lo through buffer 0, load fragments ----
    uint32_t qh[4][4], ql[4][4];
    for (int u = tid; u < 1024; u += 256) {
        int r = u >> 3, c = u & 7;
        *(uint4*)(smem + r * 144 + c * 16) = *(const uint4*)(Qh + hb + (size_t)(q0 + r) * DK_ + c * 8);
    }
    __syncthreads();
    #pragma unroll
    for (int kf = 0; kf < 4; kf++)
        ldsm4(qh[kf], ldsm_addr(sb + (w * 16) * 144 + kf * 32, lane, 144));
    __syncthreads();
    for (int u = tid; u < 1024; u += 256) {
        int r = u >> 3, c = u & 7;
        *(uint4*)(smem + r * 144 + c * 16) = *(const uint4*)(Ql + hb + (size_t)(q0 + r) * DK_ + c * 8);
    }
    __syncthreads();
    #pragma unroll
    for (int kf = 0; kf < 4; kf++)
        ldsm4(ql[kf], ldsm_addr(sb + (w * 16) * 144 + kf * 32, lane, 144));
    __syncthreads();   // all Q fragment reads complete before buffer 0 is reused

    auto loadTile = [&](int t, int buf) {
        const int kt = t * 64;
        #pragma unroll
        for (int i = 0; i < 8; i++) {
            int u = tid + i * 256;
            int arr = u >> 9, idx = u & 511, r = idx >> 3, c = idx & 7;
            const bf16* src = (arr == 0 ? Kh : arr == 1 ? Kl : arr == 2 ? Vh : Vl)
                              + hb + (size_t)(kt + r) * DK_ + c * 8;
            CP_ASYNC16(sb + buf * ASTAGE + arr * 9216 + r * 144 + c * 16, src);
        }
    };

    float acc[8][4];
    #pragma unroll
    for (int j = 0; j < 8; j++)
        #pragma unroll
        for (int e = 0; e < 4; e++) acc[j][e] = 0.0f;
    float ls0 = 0.0f, ls1 = 0.0f;

    loadTile(0, 0); CP_COMMIT();

    for (int t = 0; t < 32; t++) {
        CP_WAIT(0);            // tile t resident in buffer t&1
        __syncthreads();       // releases buffer (t+1)&1 (consumed at t-1)
        if (t + 1 < 32) { loadTile(t + 1, (t + 1) & 1); CP_COMMIT(); }
        const uint32_t off = sb + (t & 1) * ASTAGE;

        // ---- S = Q K^T ----
        float sc[8][4];
        #pragma unroll
        for (int j = 0; j < 8; j++)
            #pragma unroll
            for (int e = 0; e < 4; e++) sc[j][e] = 0.0f;
        #pragma unroll
        for (int kf = 0; kf < 4; kf++) {
            uint32_t kb[4][4], kl2[4][4];
            #pragma unroll
            for (int nt = 0; nt < 4; nt++) {
                uint32_t base = off + (nt * 16) * 144 + kf * 32;
                ldsm4(kb[nt],  ldsm_addr(base, lane, 144));
                ldsm4(kl2[nt], ldsm_addr(base + 9216, lane, 144));
            }
            #pragma unroll
            for (int pr = 0; pr < 3; pr++)
                #pragma unroll
                for (int nt = 0; nt < 4; nt++) {
                    const uint32_t* A  = (pr == 2) ? ql[kf] : qh[kf];
                    const uint32_t* Bq = (pr == 1) ? kl2[nt] : kb[nt];
                    mma_bf16(sc[2*nt],   A, Bq[0], Bq[2]);
                    mma_bf16(sc[2*nt+1], A, Bq[1], Bq[3]);
                }
        }

        // ---- p = table(s) via lerp, accumulate row sums ----
        #pragma unroll
        for (int j = 0; j < 8; j++) {
            #pragma unroll
            for (int e = 0; e < 4; e++) {
                float tt = (sc[j][e] - TAB_LO) * TAB_INVH;
                tt = fminf(fmaxf(tt, 0.0f), 4095.0f);
                int i0 = (int)tt;
                float fr = tt - (float)i0;
                float2 tv = tabp[i0];
                sc[j][e] = fmaf(fr, tv.y, tv.x);
            }
            ls0 += sc[j][0] + sc[j][1];
            ls1 += sc[j][2] + sc[j][3];
        }

        // ---- re-pipe P to A-fragments, hi/lo split ----
        uint32_t ph[4][4], pl[4][4];
        #pragma unroll
        for (int kf = 0; kf < 4; kf++) {
            int j0 = 2 * kf;
            float r0a, r0b, r1a, r1b, r2a, r2b, r3a, r3b;
            ph[kf][0] = pack_hi(sc[j0][0],   sc[j0][1],   r0a, r0b);
            ph[kf][1] = pack_hi(sc[j0][2],   sc[j0][3],   r1a, r1b);
            ph[kf][2] = pack_hi(sc[j0+1][0], sc[j0+1][1], r2a, r2b);
            ph[kf][3] = pack_hi(sc[j0+1][2], sc[j0+1][3], r3a, r3b);
            pl[kf][0] = pack2(r0a, r0b);
            pl[kf][1] = pack2(r1a, r1b);
            pl[kf][2] = pack2(r2a, r2b);
            pl[kf][3] = pack2(r3a, r3b);
        }

        // ---- acc += P V ----
        #pragma unroll
        for (int kf = 0; kf < 4; kf++) {
            uint32_t vb[4][4], vl2[4][4];
            #pragma unroll
            for (int dt = 0; dt < 4; dt++) {
                uint32_t base = off + 18432 + (kf * 16) * 144 + dt * 32;
                ldsm4t(vb[dt],  ldsm_addr(base, lane, 144));
                ldsm4t(vl2[dt], ldsm_addr(base + 9216, lane, 144));
            }
            #pragma unroll
            for (int pr = 0; pr < 3; pr++)
                #pragma unroll
                for (int dt = 0; dt < 4; dt++) {
                    const uint32_t* A  = (pr == 2) ? pl[kf] : ph[kf];
                    const uint32_t* Bq = (pr == 1) ? vl2[dt] : vb[dt];
                    mma_bf16(acc[2*dt],   A, Bq[0], Bq[1]);
                    mma_bf16(acc[2*dt+1], A, Bq[2], Bq[3]);
                }
        }
    }

    // ---- normalize and write bf16 hi/lo, flat [M, D] layout ----
    ls0 += __shfl_xor_sync(0xffffffffu, ls0, 1);
    ls0 += __shfl_xor_sync(0xffffffffu, ls0, 2);
    ls1 += __shfl_xor_sync(0xffffffffu, ls1, 1);
    ls1 += __shfl_xor_sync(0xffffffffu, ls1, 2);
    float inv0 = 1.0f / ls0, inv1 = 1.0f / ls1;
    int r0 = q0 + w * 16 + (lane >> 2);
    int bb = bh >> 4, h = bh & 15;
    #pragma unroll
    for (int j = 0; j < 8; j++) {
        int dk = j * 8 + 2 * (lane & 3);
        size_t p0 = ((size_t)(bb * S_ + r0)) * D_ + h * 64 + dk;
        size_t p1 = ((size_t)(bb * S_ + r0 + 8)) * D_ + h * 64 + dk;
        float ra, rbx;
        uint32_t h2 = pack_hi(acc[j][0] * inv0, acc[j][1] * inv0, ra, rbx);
        *(uint32_t*)(Ohi + p0) = h2;
        *(uint32_t*)(Olo + p0) = pack2(ra, rbx);
        h2 = pack_hi(acc[j][2] * inv1, acc[j][3] * inv1, ra, rbx);
        *(uint32_t*)(Ohi + p1) = h2;
        *(uint32_t*)(Olo + p1) = pack2(ra, rbx);
    }
}

// =====================================================================
// launch
// =====================================================================
extern "C" void kernel_launch(void* const* d_in, const int* in_sizes, int n_in,
                              void* d_out, int out_size) {
    (void)in_sizes; (void)n_in; (void)out_size;
    const float* query   = (const float*)d_in[0];
    const float* key_in  = (const float*)d_in[1];
    const float* value   = (const float*)d_in[2];
    const float* w_q     = (const float*)d_in[3];
    const float* b_q     = (const float*)d_in[4];
    const float* w_k     = (const float*)d_in[5];
    const float* b_k     = (const float*)d_in[6];
    const float* w_v     = (const float*)d_in[7];
    const float* b_v     = (const float*)d_in[8];
    const float* w_o     = (const float*)d_in[9];
    const float* b_o     = (const float*)d_in[10];
    const float* centers = (const float*)d_in[11];
    const float* widths  = (const float*)d_in[12];
    const float* temp    = (const float*)d_in[13];
    float* out = (float*)d_out;

    bf16 *pIhi, *pIlo, *pWhi, *pWlo, *pAhi, *pAlo;
    bf16 *pQhi, *pQlo, *pKhi, *pKlo, *pVhi, *pVlo;
    cudaGetSymbolAddress((void**)&pIhi, g_i3hi);
    cudaGetSymbolAddress((void**)&pIlo, g_i3lo);
    cudaGetSymbolAddress((void**)&pWhi, g_w4hi);
    cudaGetSymbolAddress((void**)&pWlo, g_w4lo);
    cudaGetSymbolAddress((void**)&pAhi, g_ahi);
    cudaGetSymbolAddress((void**)&pAlo, g_alo);
    cudaGetSymbolAddress((void**)&pQhi, g_Qhi);
    cudaGetSymbolAddress((void**)&pQlo, g_Qlo);
    cudaGetSymbolAddress((void**)&pKhi, g_Khi);
    cudaGetSymbolAddress((void**)&pKlo, g_Klo);
    cudaGetSymbolAddress((void**)&pVhi, g_Vhi);
    cudaGetSymbolAddress((void**)&pVlo, g_Vlo);

    cudaFuncSetAttribute(gemm_mma<0>, cudaFuncAttributeMaxDynamicSharedMemorySize, GEMM_SMEM);
    cudaFuncSetAttribute(gemm_mma<1>, cudaFuncAttributeMaxDynamicSharedMemorySize, GEMM_SMEM);
    cudaFuncSetAttribute(attn_mma, cudaFuncAttributeMaxDynamicSharedMemorySize, AT_SMEM);

    const size_t NIN = (size_t)M_TOT * D_;   // elements per input buffer
    const size_t NWW = (size_t)D_ * D_;      // elements per weight buffer
    dim3 ggrid(D_ / 128, M_TOT / 128);       // (8, 32)

    build_table<<<(TAB_N + 256) / 256, 256>>>(centers, widths, temp);

    // all splits in one launch
    int total = 3 * NIN4 + 4 * NWW4;
    split_all<<<(total + 255) / 256, 256>>>(query, key_in, value, w_q, w_k, w_v, w_o);

    // projections (fold 1/sqrt(DK)=0.125 into Q)
    gemm_mma<1><<<ggrid, 256, GEMM_SMEM>>>(pIhi, pIlo, pWhi, pWlo, b_q, 0.125f,
                                           nullptr, pQhi, pQlo);
    gemm_mma<1><<<ggrid, 256, GEMM_SMEM>>>(pIhi + NIN, pIlo + NIN, pWhi + NWW, pWlo + NWW,
                                           b_k, 1.0f, nullptr, pKhi, pKlo);
    gemm_mma<1><<<ggrid, 256, GEMM_SMEM>>>(pIhi + 2*NIN, pIlo + 2*NIN, pWhi + 2*NWW, pWlo + 2*NWW,
                                           b_v, 1.0f, nullptr, pVhi, pVlo);

    // attention (writes bf16 hi/lo directly)
    attn_mma<<<dim3(S_ / 128, B_ * H_), 256, AT_SMEM>>>(pQhi, pQlo, pKhi, pKlo,
                                                        pVhi, pVlo, pAhi, pAlo);

    // output projection
    gemm_mma<0><<<ggrid, 256, GEMM_SMEM>>>(pAhi, pAlo, pWhi + 3*NWW, pWlo + 3*NWW,
                                           b_o, 1.0f, out, nullptr, nullptr);
}

// round 12
// speedup vs baseline: 3.9522x; 1.4574x over previous
#include <cuda_runtime.h>
#include <cuda_fp16.h>
#include <cstdint>
#include <math.h>

#define B_   2
#define S_   2048
#define D_   1024
#define H_   16
#define DK_  64
#define M_TOT (B_*S_)          // 4096

#define TAB_N   4096
#define TAB_LO  (-8.0f)
#define TAB_INVH 256.0f
#define TAB_SCALE 0.00390625f   // 2^-8: keeps P within fp16 range; cancels in 1/sum

// ---- scratch (device globals) ----
__device__ float g_tab[TAB_N+1];
__device__ __half g_i3hi[3][(size_t)M_TOT*D_];   // split inputs: q, k, v
__device__ __half g_i3lo[3][(size_t)M_TOT*D_];
__device__ __half g_w4hi[4][(size_t)D_*D_];      // weights (single-rounded fp16)
__device__ __half g_ahi[(size_t)M_TOT*D_];       // attention output hi/lo
__device__ __half g_alo[(size_t)M_TOT*D_];
__device__ __half g_Qhi[B_*H_*S_*DK_];
__device__ __half g_Qlo[B_*H_*S_*DK_];
__device__ __half g_Kh[B_*H_*S_*DK_];            // K, V single-rounded
__device__ __half g_Vh[B_*H_*S_*DK_];

// =====================================================================
// PTX helpers (target-independent sm_80-class instructions)
// =====================================================================
__device__ __forceinline__ uint32_t smem_u32(const void* p) {
    uint32_t a;
    asm("{ .reg .u64 t; cvta.to.shared.u64 t, %1; cvt.u32.u64 %0, t; }" : "=r"(a) : "l"(p));
    return a;
}
#define CP_ASYNC16(dst, src) asm volatile("cp.async.ca.shared.global [%0], [%1], 16;" :: "r"(dst), "l"(src))
#define CP_COMMIT() asm volatile("cp.async.commit_group;" ::: "memory")
#define CP_WAIT(n)  asm volatile("cp.async.wait_group %0;" :: "n"(n) : "memory")

__device__ __forceinline__ void ldsm4(uint32_t* r, uint32_t a) {
    asm volatile("ldmatrix.sync.aligned.m8n8.x4.shared.b16 {%0,%1,%2,%3}, [%4];"
        : "=r"(r[0]),"=r"(r[1]),"=r"(r[2]),"=r"(r[3]) : "r"(a));
}
__device__ __forceinline__ void ldsm4t(uint32_t* r, uint32_t a) {
    asm volatile("ldmatrix.sync.aligned.m8n8.x4.trans.shared.b16 {%0,%1,%2,%3}, [%4];"
        : "=r"(r[0]),"=r"(r[1]),"=r"(r[2]),"=r"(r[3]) : "r"(a));
}
__device__ __forceinline__ void mma_fp16(float* d, const uint32_t* a, uint32_t b0, uint32_t b1) {
    asm volatile("mma.sync.aligned.m16n8k16.row.col.f32.f16.f16.f32 "
        "{%0,%1,%2,%3}, {%4,%5,%6,%7}, {%8,%9}, {%0,%1,%2,%3};"
        : "+f"(d[0]),"+f"(d[1]),"+f"(d[2]),"+f"(d[3])
        : "r"(a[0]),"r"(a[1]),"r"(a[2]),"r"(a[3]), "r"(b0),"r"(b1));
}
__device__ __forceinline__ uint32_t ldsm_addr(uint32_t base, int lane, int strideB) {
    return base + (uint32_t)((lane & 15) * strideB + ((lane >> 4) << 4));
}
__device__ __forceinline__ uint32_t packh_hi(float a, float b, float& ra, float& rb) {
    __half2 h = __floats2half2_rn(a, b);
    ra = a - __low2float(h);
    rb = b - __high2float(h);
    return *reinterpret_cast<uint32_t*>(&h);
}
__device__ __forceinline__ uint32_t packh2(float a, float b) {
    __half2 h = __floats2half2_rn(a, b);
    return *reinterpret_cast<uint32_t*>(&h);
}

// =====================================================================
// 0) batched split: inputs -> fp16 hi+lo; weights -> fp16 hi only
// =====================================================================
#define NIN4 (M_TOT*D_/4)   // 1048576
#define NWW4 (D_*D_/4)      // 262144

__global__ void split_all(const float* __restrict__ q, const float* __restrict__ k,
                          const float* __restrict__ v, const float* __restrict__ wq,
                          const float* __restrict__ wk, const float* __restrict__ wv,
                          const float* __restrict__ wo) {
    int i = blockIdx.x * blockDim.x + threadIdx.x;
    if (i < 3 * NIN4) {
        int seg = i / NIN4;
        size_t off = (size_t)(i - seg * NIN4);
        const float* src = seg == 0 ? q : seg == 1 ? k : v;
        float4 vv = ((const float4*)src)[off];
        float r0, r1, r2, r3;
        uint32_t h0 = packh_hi(vv.x, vv.y, r0, r1);
        uint32_t h1 = packh_hi(vv.z, vv.w, r2, r3);
        *(uint2*)(g_i3hi[seg] + 4 * off) = make_uint2(h0, h1);
        *(uint2*)(g_i3lo[seg] + 4 * off) = make_uint2(packh2(r0, r1), packh2(r2, r3));
    } else {
        int j = i - 3 * NIN4;
        if (j >= 4 * NWW4) return;
        int seg = j / NWW4;
        size_t off = (size_t)(j - seg * NWW4);
        const float* src = seg == 0 ? wq : seg == 1 ? wk : seg == 2 ? wv : wo;
        float4 vv = ((const float4*)src)[off];
        *(uint2*)(g_w4hi[seg] + 4 * off) = make_uint2(packh2(vv.x, vv.y), packh2(vv.z, vv.w));
    }
}

// =====================================================================
// 1) table: g(s) = exp( sum_i gauss_i(s) / (3 T) ) * 2^-8
// =====================================================================
__global__ void build_table(const float* __restrict__ centers,
                            const float* __restrict__ widths,
                            const float* __restrict__ temp) {
    int i = blockIdx.x * blockDim.x + threadIdx.x;
    if (i > TAB_N) return;
    float s = TAB_LO + (float)i * (1.0f / TAB_INVH);
    float acc = 0.0f;
    #pragma unroll 1
    for (int j = 0; j < H_*3; j++) {
        float c = centers[j];
        float w = widths[j];
        float d = s - c;
        acc += expf(-(d*d) / (2.0f * w * w));
    }
    g_tab[i] = expf(acc / (3.0f * temp[0])) * TAB_SCALE;
}

// =====================================================================
// 2) HMMA GEMM: C = (Ahi+Alo) @ Wh^T + bias  (fp16 2-product)
//    128x128 tile, k-chunk 32, 8 warps (4m x 2n), 2-stage cp.async.
//    MODE 0: fp32 flat store. MODE 1: head layout hi+lo. MODE 2: head hi only.
// =====================================================================
#define GK 32
#define GSTRIDE 80              // bytes per smem row (32+8 fp16)
#define GBUF 10240              // one array: 128 rows * 80B
#define GSTAGE (3*GBUF)         // 30720 (Ahi, Alo, Wh)
#define GEMM_SMEM (2*GSTAGE)    // 61440

template<int MODE>
__global__ void __launch_bounds__(256)
gemm_mma(const __half* __restrict__ Agh, const __half* __restrict__ Agl,
         const __half* __restrict__ Wgh,
         const float* __restrict__ bias, float scale,
         float* __restrict__ C, __half* __restrict__ Chi, __half* __restrict__ Clo) {
    extern __shared__ char smem[];
    const uint32_t sb = smem_u32(smem);
    const int tid = threadIdx.x, w = tid >> 5, lane = tid & 31;
    const int m0 = blockIdx.y * 128, n0 = blockIdx.x * 128;
    const int wm = (w >> 1) * 32, wn = (w & 1) * 64;

    float acc[2][8][4];
    #pragma unroll
    for (int a = 0; a < 2; a++)
        #pragma unroll
        for (int b = 0; b < 8; b++)
            #pragma unroll
            for (int c = 0; c < 4; c++) acc[a][b][c] = 0.0f;

    auto loadChunk = [&](int c, int buf) {
        const uint32_t off = sb + buf * GSTAGE;
        const int k0 = c * GK;
        #pragma unroll
        for (int i = 0; i < 6; i++) {
            int u = tid + i * 256;
            int arr = u >> 9, idx = u & 511;
            int r = idx >> 2, cc = idx & 3;
            const __half* src;
            if      (arr == 0) src = Agh + (size_t)(m0 + r) * D_ + k0 + cc * 8;
            else if (arr == 1) src = Agl + (size_t)(m0 + r) * D_ + k0 + cc * 8;
            else               src = Wgh + (size_t)(n0 + r) * D_ + k0 + cc * 8;
            CP_ASYNC16(off + arr * GBUF + r * GSTRIDE + cc * 16, src);
        }
    };
    auto compute = [&](int buf) {
        const uint32_t off = sb + buf * GSTAGE;
        uint32_t Ah[2][2][4], Al[2][2][4];
        #pragma unroll
        for (int mi = 0; mi < 2; mi++)
            #pragma unroll
            for (int kf = 0; kf < 2; kf++) {
                uint32_t base = off + (wm + mi * 16) * GSTRIDE + kf * 32;
                ldsm4(Ah[mi][kf], ldsm_addr(base, lane, GSTRIDE));
                ldsm4(Al[mi][kf], ldsm_addr(base + GBUF, lane, GSTRIDE));
            }
        #pragma unroll
        for (int kf = 0; kf < 2; kf++) {
            uint32_t Bh[4][4];
            #pragma unroll
            for (int nt = 0; nt < 4; nt++) {
                uint32_t base = off + 2 * GBUF + (wn + nt * 16) * GSTRIDE + kf * 32;
                ldsm4(Bh[nt], ldsm_addr(base, lane, GSTRIDE));
            }
            #pragma unroll
            for (int pr = 0; pr < 2; pr++)
                #pragma unroll
                for (int mi = 0; mi < 2; mi++)
                    #pragma unroll
                    for (int nt = 0; nt < 4; nt++) {
                        const uint32_t* A = (pr == 1) ? Al[mi][kf] : Ah[mi][kf];
                        mma_fp16(acc[mi][2*nt],   A, Bh[nt][0], Bh[nt][2]);
                        mma_fp16(acc[mi][2*nt+1], A, Bh[nt][1], Bh[nt][3]);
                    }
        }
    };

    loadChunk(0, 0); CP_COMMIT();
    for (int c = 0; c < 32; c++) {
        CP_WAIT(0);            // chunk c resident in buffer c&1
        __syncthreads();       // also releases buffer (c+1)&1 (computed at c-1)
        if (c + 1 < 32) { loadChunk(c + 1, (c + 1) & 1); CP_COMMIT(); }
        compute(c & 1);        // overlaps with in-flight load of chunk c+1
    }

    // epilogue
    #pragma unroll
    for (int mi = 0; mi < 2; mi++) {
        int r0 = m0 + wm + mi * 16 + (lane >> 2);
        #pragma unroll
        for (int ni = 0; ni < 8; ni++) {
            int col = n0 + wn + ni * 8 + 2 * (lane & 3);
            float b0v = __ldg(bias + col), b1v = __ldg(bias + col + 1);
            #pragma unroll
            for (int rr = 0; rr < 2; rr++) {
                int row = r0 + rr * 8;
                float v0 = (acc[mi][ni][2*rr]   + b0v) * scale;
                float v1 = (acc[mi][ni][2*rr+1] + b1v) * scale;
                if (MODE == 0) {
                    *(float2*)(C + (size_t)row * D_ + col) = make_float2(v0, v1);
                } else {
                    int bb = row >> 11, s = row & 2047, h = col >> 6, dk = col & 63;
                    size_t p = ((size_t)((bb * H_ + h) * S_ + s)) * DK_ + dk;
                    if (MODE == 1) {
                        float ra, rb;
                        uint32_t hi2 = packh_hi(v0, v1, ra, rb);
                        *(uint32_t*)(Chi + p) = hi2;
                        *(uint32_t*)(Clo + p) = packh2(ra, rb);
                    } else {
                        *(uint32_t*)(Chi + p) = packh2(v0, v1);
                    }
                }
            }
        }
    }
}

// =====================================================================
// 3) HMMA flash attention, fp16 2-product, 2-stage pipelined K/V tiles.
//    q-tile 128 (8 warps x 16 rows), k-tile 64. Writes fp16 hi/lo out.
//    stage buf: Kh@0 Vh@9216 (64 rows x 144B). Q staged through buf 0.
// =====================================================================
#define ASTAGE 18432
#define AT_SMEM (2*ASTAGE + TAB_N*8)   // 36864 + 32768 = 69632

__global__ void __launch_bounds__(256)
attn_mma(const __half* __restrict__ Qh, const __half* __restrict__ Ql,
         const __half* __restrict__ Kh, const __half* __restrict__ Vh,
         __half* __restrict__ Ohi, __half* __restrict__ Olo) {
    extern __shared__ char smem[];
    const uint32_t sb = smem_u32(smem);
    float2* tabp = (float2*)(smem + 2 * ASTAGE);
    const int tid = threadIdx.x, w = tid >> 5, lane = tid & 31;
    const int bh = blockIdx.y, q0 = blockIdx.x * 128;
    const size_t hb = (size_t)bh * S_ * DK_;

    for (int i = tid; i < TAB_N; i += 256) {
        float a = g_tab[i];
        tabp[i] = make_float2(a, g_tab[i + 1] - a);
    }

    // ---- stage Q hi/lo through buffer 0 (18432B = 128 rows x 144B) ----
    uint32_t qh[4][4], ql[4][4];
    for (int u = tid; u < 1024; u += 256) {
        int r = u >> 3, c = u & 7;
        *(uint4*)(smem + r * 144 + c * 16) = *(const uint4*)(Qh + hb + (size_t)(q0 + r) * DK_ + c * 8);
    }
    __syncthreads();
    #pragma unroll
    for (int kf = 0; kf < 4; kf++)
        ldsm4(qh[kf], ldsm_addr(sb + (w * 16) * 144 + kf * 32, lane, 144));
    __syncthreads();
    for (int u = tid; u < 1024; u += 256) {
        int r = u >> 3, c = u & 7;
        *(uint4*)(smem + r * 144 + c * 16) = *(const uint4*)(Ql + hb + (size_t)(q0 + r) * DK_ + c * 8);
    }
    __syncthreads();
    #pragma unroll
    for (int kf = 0; kf < 4; kf++)
        ldsm4(ql[kf], ldsm_addr(sb + (w * 16) * 144 + kf * 32, lane, 144));
    __syncthreads();   // all Q fragment reads complete before buffer 0 reuse

    auto loadTile = [&](int t, int buf) {
        const int kt = t * 64;
        #pragma unroll
        for (int i = 0; i < 4; i++) {
            int u = tid + i * 256;
            int arr = u >> 9, idx = u & 511, r = idx >> 3, c = idx & 7;
            const __half* src = (arr == 0 ? Kh : Vh) + hb + (size_t)(kt + r) * DK_ + c * 8;
            CP_ASYNC16(sb + buf * ASTAGE + arr * 9216 + r * 144 + c * 16, src);
        }
    };

    float acc[8][4];
    #pragma unroll
    for (int j = 0; j < 8; j++)
        #pragma unroll
        for (int e = 0; e < 4; e++) acc[j][e] = 0.0f;
    float ls0 = 0.0f, ls1 = 0.0f;

    loadTile(0, 0); CP_COMMIT();

    for (int t = 0; t < 32; t++) {
        CP_WAIT(0);            // tile t resident in buffer t&1
        __syncthreads();       // releases buffer (t+1)&1 (consumed at t-1)
        if (t + 1 < 32) { loadTile(t + 1, (t + 1) & 1); CP_COMMIT(); }
        const uint32_t off = sb + (t & 1) * ASTAGE;

        // ---- S = (Qh+Ql) K^T ----
        float sc[8][4];
        #pragma unroll
        for (int j = 0; j < 8; j++)
            #pragma unroll
            for (int e = 0; e < 4; e++) sc[j][e] = 0.0f;
        #pragma unroll
        for (int kf = 0; kf < 4; kf++) {
            uint32_t kb[4][4];
            #pragma unroll
            for (int nt = 0; nt < 4; nt++)
                ldsm4(kb[nt], ldsm_addr(off + (nt * 16) * 144 + kf * 32, lane, 144));
            #pragma unroll
            for (int pr = 0; pr < 2; pr++)
                #pragma unroll
                for (int nt = 0; nt < 4; nt++) {
                    const uint32_t* A = (pr == 1) ? ql[kf] : qh[kf];
                    mma_fp16(sc[2*nt],   A, kb[nt][0], kb[nt][2]);
                    mma_fp16(sc[2*nt+1], A, kb[nt][1], kb[nt][3]);
                }
        }

        // ---- p = table(s) via lerp (scaled by 2^-8), accumulate row sums ----
        #pragma unroll
        for (int j = 0; j < 8; j++) {
            #pragma unroll
            for (int e = 0; e < 4; e++) {
                float tt = (sc[j][e] - TAB_LO) * TAB_INVH;
                tt = fminf(fmaxf(tt, 0.0f), 4095.0f);
                int i0 = (int)tt;
                float fr = tt - (float)i0;
                float2 tv = tabp[i0];
                sc[j][e] = fmaf(fr, tv.y, tv.x);
            }
            ls0 += sc[j][0] + sc[j][1];
            ls1 += sc[j][2] + sc[j][3];
        }

        // ---- re-pipe P to A-fragments, fp16 hi/lo split ----
        uint32_t ph[4][4], pl[4][4];
        #pragma unroll
        for (int kf = 0; kf < 4; kf++) {
            int j0 = 2 * kf;
            float r0a, r0b, r1a, r1b, r2a, r2b, r3a, r3b;
            ph[kf][0] = packh_hi(sc[j0][0],   sc[j0][1],   r0a, r0b);
            ph[kf][1] = packh_hi(sc[j0][2],   sc[j0][3],   r1a, r1b);
            ph[kf][2] = packh_hi(sc[j0+1][0], sc[j0+1][1], r2a, r2b);
            ph[kf][3] = packh_hi(sc[j0+1][2], sc[j0+1][3], r3a, r3b);
            pl[kf][0] = packh2(r0a, r0b);
            pl[kf][1] = packh2(r1a, r1b);
            pl[kf][2] = packh2(r2a, r2b);
            pl[kf][3] = packh2(r3a, r3b);
        }

        // ---- acc += (Ph+Pl) V ----
        #pragma unroll
        for (int kf = 0; kf < 4; kf++) {
            uint32_t vb[4][4];
            #pragma unroll
            for (int dt = 0; dt < 4; dt++)
                ldsm4t(vb[dt], ldsm_addr(off + 9216 + (kf * 16) * 144 + dt * 32, lane, 144));
            #pragma unroll
            for (int pr = 0; pr < 2; pr++)
                #pragma unroll
                for (int dt = 0; dt < 4; dt++) {
                    const uint32_t* A = (pr == 1) ? pl[kf] : ph[kf];
                    mma_fp16(acc[2*dt],   A, vb[dt][0], vb[dt][1]);
                    mma_fp16(acc[2*dt+1], A, vb[dt][2], vb[dt][3]);
                }
        }
    }

    // ---- normalize (table scale cancels) and write fp16 hi/lo ----
    ls0 += __shfl_xor_sync(0xffffffffu, ls0, 1);
    ls0 += __shfl_xor_sync(0xffffffffu, ls0, 2);
    ls1 += __shfl_xor_sync(0xffffffffu, ls1, 1);
    ls1 += __shfl_xor_sync(0xffffffffu, ls1, 2);
    float inv0 = 1.0f / ls0, inv1 = 1.0f / ls1;
    int r0 = q0 + w * 16 + (lane >> 2);
    int bb = bh >> 4, h = bh & 15;
    #pragma unroll
    for (int j = 0; j < 8; j++) {
        int dk = j * 8 + 2 * (lane & 3);
        size_t p0 = ((size_t)(bb * S_ + r0)) * D_ + h * 64 + dk;
        size_t p1 = ((size_t)(bb * S_ + r0 + 8)) * D_ + h * 64 + dk;
        float ra, rbx;
        uint32_t h2 = packh_hi(acc[j][0] * inv0, acc[j][1] * inv0, ra, rbx);
        *(uint32_t*)(Ohi + p0) = h2;
        *(uint32_t*)(Olo + p0) = packh2(ra, rbx);
        h2 = packh_hi(acc[j][2] * inv1, acc[j][3] * inv1, ra, rbx);
        *(uint32_t*)(Ohi + p1) = h2;
        *(uint32_t*)(Olo + p1) = packh2(ra, rbx);
    }
}

// =====================================================================
// launch
// =====================================================================
extern "C" void kernel_launch(void* const* d_in, const int* in_sizes, int n_in,
                              void* d_out, int out_size) {
    (void)in_sizes; (void)n_in; (void)out_size;
    const float* query   = (const float*)d_in[0];
    const float* key_in  = (const float*)d_in[1];
    const float* value   = (const float*)d_in[2];
    const float* w_q     = (const float*)d_in[3];
    const float* b_q     = (const float*)d_in[4];
    const float* w_k     = (const float*)d_in[5];
    const float* b_k     = (const float*)d_in[6];
    const float* w_v     = (const float*)d_in[7];
    const float* b_v     = (const float*)d_in[8];
    const float* w_o     = (const float*)d_in[9];
    const float* b_o     = (const float*)d_in[10];
    const float* centers = (const float*)d_in[11];
    const float* widths  = (const float*)d_in[12];
    const float* temp    = (const float*)d_in[13];
    float* out = (float*)d_out;

    __half *pIhi, *pIlo, *pWhi, *pAhi, *pAlo;
    __half *pQhi, *pQlo, *pKh, *pVh;
    cudaGetSymbolAddress((void**)&pIhi, g_i3hi);
    cudaGetSymbolAddress((void**)&pIlo, g_i3lo);
    cudaGetSymbolAddress((void**)&pWhi, g_w4hi);
    cudaGetSymbolAddress((void**)&pAhi, g_ahi);
    cudaGetSymbolAddress((void**)&pAlo, g_alo);
    cudaGetSymbolAddress((void**)&pQhi, g_Qhi);
    cudaGetSymbolAddress((void**)&pQlo, g_Qlo);
    cudaGetSymbolAddress((void**)&pKh,  g_Kh);
    cudaGetSymbolAddress((void**)&pVh,  g_Vh);

    cudaFuncSetAttribute(gemm_mma<0>, cudaFuncAttributeMaxDynamicSharedMemorySize, GEMM_SMEM);
    cudaFuncSetAttribute(gemm_mma<1>, cudaFuncAttributeMaxDynamicSharedMemorySize, GEMM_SMEM);
    cudaFuncSetAttribute(gemm_mma<2>, cudaFuncAttributeMaxDynamicSharedMemorySize, GEMM_SMEM);
    cudaFuncSetAttribute(attn_mma, cudaFuncAttributeMaxDynamicSharedMemorySize, AT_SMEM);

    const size_t NIN = (size_t)M_TOT * D_;   // elements per input buffer
    const size_t NWW = (size_t)D_ * D_;      // elements per weight buffer
    dim3 ggrid(D_ / 128, M_TOT / 128);       // (8, 32)

    build_table<<<(TAB_N + 256) / 256, 256>>>(centers, widths, temp);

    // all splits in one launch
    int total = 3 * NIN4 + 4 * NWW4;
    split_all<<<(total + 255) / 256, 256>>>(query, key_in, value, w_q, w_k, w_v, w_o);

    // projections (fold 1/sqrt(DK)=0.125 into Q); Q needs hi+lo, K/V hi only
    gemm_mma<1><<<ggrid, 256, GEMM_SMEM>>>(pIhi, pIlo, pWhi, b_q, 0.125f,
                                           nullptr, pQhi, pQlo);
    gemm_mma<2><<<ggrid, 256, GEMM_SMEM>>>(pIhi + NIN, pIlo + NIN, pWhi + NWW,
                                           b_k, 1.0f, nullptr, pKh, nullptr);
    gemm_mma<2><<<ggrid, 256, GEMM_SMEM>>>(pIhi + 2*NIN, pIlo + 2*NIN, pWhi + 2*NWW,
                                           b_v, 1.0f, nullptr, pVh, nullptr);

    // attention (fp16 2-product; writes fp16 hi/lo directly)
    attn_mma<<<dim3(S_ / 128, B_ * H_), 256, AT_SMEM>>>(pQhi, pQlo, pKh, pVh,
                                                        pAhi, pAlo);

    // output projection
    gemm_mma<0><<<ggrid, 256, GEMM_SMEM>>>(pAhi, pAlo, pWhi + 3*NWW,
                                           b_o, 1.0f, out, nullptr, nullptr);
}

// round 13
// speedup vs baseline: 5.7050x; 1.4435x over previous
#include <cuda_runtime.h>
#include <cuda_fp16.h>
#include <cstdint>
#include <math.h>

#define B_   2
#define S_   2048
#define D_   1024
#define H_   16
#define DK_  64
#define M_TOT (B_*S_)          // 4096

#define TAB_N   4096
#define TAB_LO  (-8.0f)
#define TAB_INVH 256.0f
#define TAB_SCALE 0.00390625f   // 2^-8: keeps P within fp16 range; cancels in 1/sum

#define NINel ((size_t)M_TOT*D_)   // 4194304
#define NWWel ((size_t)D_*D_)      // 1048576

// ---- scratch (device globals) ----
__device__ float g_tab[TAB_N+1];
__device__ __half g_ih[3][NINel];     // fp16 inputs: q, k, v
__device__ __half g_wh[4][NWWel];     // fp16 weights: wq, wk, wv, wo
__device__ __half g_qkv[3][NINel];    // projected Q, K, V (head layout)
__device__ __half g_ah[NINel];        // attention output (flat [M, D])

// =====================================================================
// PTX helpers (target-independent sm_80-class instructions)
// =====================================================================
__device__ __forceinline__ uint32_t smem_u32(const void* p) {
    uint32_t a;
    asm("{ .reg .u64 t; cvta.to.shared.u64 t, %1; cvt.u32.u64 %0, t; }" : "=r"(a) : "l"(p));
    return a;
}
#define CP_ASYNC16(dst, src) asm volatile("cp.async.ca.shared.global [%0], [%1], 16;" :: "r"(dst), "l"(src))
#define CP_COMMIT() asm volatile("cp.async.commit_group;" ::: "memory")
#define CP_WAIT(n)  asm volatile("cp.async.wait_group %0;" :: "n"(n) : "memory")

__device__ __forceinline__ void ldsm4(uint32_t* r, uint32_t a) {
    asm volatile("ldmatrix.sync.aligned.m8n8.x4.shared.b16 {%0,%1,%2,%3}, [%4];"
        : "=r"(r[0]),"=r"(r[1]),"=r"(r[2]),"=r"(r[3]) : "r"(a));
}
__device__ __forceinline__ void ldsm4t(uint32_t* r, uint32_t a) {
    asm volatile("ldmatrix.sync.aligned.m8n8.x4.trans.shared.b16 {%0,%1,%2,%3}, [%4];"
        : "=r"(r[0]),"=r"(r[1]),"=r"(r[2]),"=r"(r[3]) : "r"(a));
}
__device__ __forceinline__ void mma_fp16(float* d, const uint32_t* a, uint32_t b0, uint32_t b1) {
    asm volatile("mma.sync.aligned.m16n8k16.row.col.f32.f16.f16.f32 "
        "{%0,%1,%2,%3}, {%4,%5,%6,%7}, {%8,%9}, {%0,%1,%2,%3};"
        : "+f"(d[0]),"+f"(d[1]),"+f"(d[2]),"+f"(d[3])
        : "r"(a[0]),"r"(a[1]),"r"(a[2]),"r"(a[3]), "r"(b0),"r"(b1));
}
__device__ __forceinline__ uint32_t ldsm_addr(uint32_t base, int lane, int strideB) {
    return base + (uint32_t)((lane & 15) * strideB + ((lane >> 4) << 4));
}
__device__ __forceinline__ uint32_t packh2(float a, float b) {
    __half2 h = __floats2half2_rn(a, b);
    return *reinterpret_cast<uint32_t*>(&h);
}

// =====================================================================
// 0) batched fp32 -> fp16 conversion: 3 inputs + 4 weights
// =====================================================================
#define NIN4 (M_TOT*D_/4)   // 1048576
#define NWW4 (D_*D_/4)      // 262144

__global__ void split_all(const float* __restrict__ q, const float* __restrict__ k,
                          const float* __restrict__ v, const float* __restrict__ wq,
                          const float* __restrict__ wk, const float* __restrict__ wv,
                          const float* __restrict__ wo) {
    int i = blockIdx.x * blockDim.x + threadIdx.x;
    const float* src; __half* dst; size_t off;
    if (i < 3 * NIN4) {
        int seg = i / NIN4; off = (size_t)(i - seg * NIN4);
        src = seg == 0 ? q : seg == 1 ? k : v;
        dst = g_ih[seg];
    } else {
        int j = i - 3 * NIN4;
        if (j >= 4 * NWW4) return;
        int seg = j / NWW4; off = (size_t)(j - seg * NWW4);
        src = seg == 0 ? wq : seg == 1 ? wk : seg == 2 ? wv : wo;
        dst = g_wh[seg];
    }
    float4 vv = ((const float4*)src)[off];
    *(uint2*)(dst + 4 * off) = make_uint2(packh2(vv.x, vv.y), packh2(vv.z, vv.w));
}

// =====================================================================
// 1) table: g(s) = exp( sum_i gauss_i(s) / (3 T) ) * 2^-8
// =====================================================================
__global__ void build_table(const float* __restrict__ centers,
                            const float* __restrict__ widths,
                            const float* __restrict__ temp) {
    int i = blockIdx.x * blockDim.x + threadIdx.x;
    if (i > TAB_N) return;
    float s = TAB_LO + (float)i * (1.0f / TAB_INVH);
    float acc = 0.0f;
    #pragma unroll 1
    for (int j = 0; j < H_*3; j++) {
        float c = centers[j];
        float w = widths[j];
        float d = s - c;
        acc += expf(-(d*d) / (2.0f * w * w));
    }
    g_tab[i] = expf(acc / (3.0f * temp[0])) * TAB_SCALE;
}

// =====================================================================
// 2) HMMA GEMM: C = A @ W^T + bias   (single fp16 product)
//    128x128 tile, k-chunk 32, 8 warps (4m x 2n), 2-stage cp.async.
//    MODE 0: O-projection, fp32 flat store, grid (8,32).
//    MODE 1: fused QKV, grid (8,32,3); z selects seg; fp16 head-layout out.
// =====================================================================
#define GK 32
#define GSTRIDE 80              // bytes per smem row (32+8 fp16)
#define GBUF 10240              // one array: 128 rows * 80B
#define GSTAGE (2*GBUF)         // 20480 (A, W)
#define GEMM_SMEM (2*GSTAGE)    // 40960

template<int MODE>
__global__ void __launch_bounds__(256)
gemm_mma(const __half* __restrict__ A0, const __half* __restrict__ W0,
         const float* __restrict__ bq, const float* __restrict__ bk,
         const float* __restrict__ bv,
         float* __restrict__ C, __half* __restrict__ Ch) {
    extern __shared__ char smem[];
    const uint32_t sb = smem_u32(smem);
    const int tid = threadIdx.x, w = tid >> 5, lane = tid & 31;
    const int m0 = blockIdx.y * 128, n0 = blockIdx.x * 128;
    const int wm = (w >> 1) * 32, wn = (w & 1) * 64;

    const __half* A = A0;
    const __half* W = W0;
    const float* bias = bq;
    __half* Chz = Ch;
    float scale = 1.0f;
    if (MODE == 1) {
        int z = blockIdx.z;
        A = A0 + (size_t)z * NINel;
        W = W0 + (size_t)z * NWWel;
        bias = z == 0 ? bq : (z == 1 ? bk : bv);
        Chz = Ch + (size_t)z * NINel;
        scale = (z == 0) ? 0.125f : 1.0f;
    }

    float acc[2][8][4];
    #pragma unroll
    for (int a = 0; a < 2; a++)
        #pragma unroll
        for (int b = 0; b < 8; b++)
            #pragma unroll
            for (int c = 0; c < 4; c++) acc[a][b][c] = 0.0f;

    auto loadChunk = [&](int c, int buf) {
        const uint32_t off = sb + buf * GSTAGE;
        const int k0 = c * GK;
        #pragma unroll
        for (int i = 0; i < 4; i++) {
            int u = tid + i * 256;
            int arr = u >> 9, idx = u & 511;
            int r = idx >> 2, cc = idx & 3;
            const __half* src = arr == 0 ? A + (size_t)(m0 + r) * D_ + k0 + cc * 8
                                         : W + (size_t)(n0 + r) * D_ + k0 + cc * 8;
            CP_ASYNC16(off + arr * GBUF + r * GSTRIDE + cc * 16, src);
        }
    };
    auto compute = [&](int buf) {
        const uint32_t off = sb + buf * GSTAGE;
        uint32_t Ah[2][2][4];
        #pragma unroll
        for (int mi = 0; mi < 2; mi++)
            #pragma unroll
            for (int kf = 0; kf < 2; kf++)
                ldsm4(Ah[mi][kf], ldsm_addr(off + (wm + mi * 16) * GSTRIDE + kf * 32, lane, GSTRIDE));
        #pragma unroll
        for (int kf = 0; kf < 2; kf++) {
            uint32_t Bh[4][4];
            #pragma unroll
            for (int nt = 0; nt < 4; nt++)
                ldsm4(Bh[nt], ldsm_addr(off + GBUF + (wn + nt * 16) * GSTRIDE + kf * 32, lane, GSTRIDE));
            #pragma unroll
            for (int mi = 0; mi < 2; mi++)
                #pragma unroll
                for (int nt = 0; nt < 4; nt++) {
                    mma_fp16(acc[mi][2*nt],   Ah[mi][kf], Bh[nt][0], Bh[nt][2]);
                    mma_fp16(acc[mi][2*nt+1], Ah[mi][kf], Bh[nt][1], Bh[nt][3]);
                }
        }
    };

    loadChunk(0, 0); CP_COMMIT();
    for (int c = 0; c < 32; c++) {
        CP_WAIT(0);            // chunk c resident in buffer c&1
        __syncthreads();       // also releases buffer (c+1)&1 (computed at c-1)
        if (c + 1 < 32) { loadChunk(c + 1, (c + 1) & 1); CP_COMMIT(); }
        compute(c & 1);        // overlaps with in-flight load of chunk c+1
    }

    // epilogue
    #pragma unroll
    for (int mi = 0; mi < 2; mi++) {
        int r0 = m0 + wm + mi * 16 + (lane >> 2);
        #pragma unroll
        for (int ni = 0; ni < 8; ni++) {
            int col = n0 + wn + ni * 8 + 2 * (lane & 3);
            float b0v = __ldg(bias + col), b1v = __ldg(bias + col + 1);
            #pragma unroll
            for (int rr = 0; rr < 2; rr++) {
                int row = r0 + rr * 8;
                float v0 = (acc[mi][ni][2*rr]   + b0v) * scale;
                float v1 = (acc[mi][ni][2*rr+1] + b1v) * scale;
                if (MODE == 0) {
                    *(float2*)(C + (size_t)row * D_ + col) = make_float2(v0, v1);
                } else {
                    int bb = row >> 11, s = row & 2047, h = col >> 6, dk = col & 63;
                    size_t p = ((size_t)((bb * H_ + h) * S_ + s)) * DK_ + dk;
                    *(uint32_t*)(Chz + p) = packh2(v0, v1);
                }
            }
        }
    }
}

// =====================================================================
// 3) HMMA flash attention, single fp16 products, 2-stage K/V pipeline.
//    q-tile 128 (8 warps x 16 rows), k-tile 64. Writes fp16 out.
//    stage buf: Kh@0 Vh@9216 (64 rows x 144B). Q staged through buf 0.
// =====================================================================
#define ASTAGE 18432
#define AT_SMEM (2*ASTAGE + TAB_N*8)   // 36864 + 32768 = 69632

__global__ void __launch_bounds__(256)
attn_mma(const __half* __restrict__ Qh, const __half* __restrict__ Kh,
         const __half* __restrict__ Vh, __half* __restrict__ Oh) {
    extern __shared__ char smem[];
    const uint32_t sb = smem_u32(smem);
    float2* tabp = (float2*)(smem + 2 * ASTAGE);
    const int tid = threadIdx.x, w = tid >> 5, lane = tid & 31;
    const int bh = blockIdx.y, q0 = blockIdx.x * 128;
    const size_t hb = (size_t)bh * S_ * DK_;

    for (int i = tid; i < TAB_N; i += 256) {
        float a = g_tab[i];
        tabp[i] = make_float2(a, g_tab[i + 1] - a);
    }

    // ---- stage Q through buffer 0, load fragments ----
    uint32_t qh[4][4];
    for (int u = tid; u < 1024; u += 256) {
        int r = u >> 3, c = u & 7;
        *(uint4*)(smem + r * 144 + c * 16) = *(const uint4*)(Qh + hb + (size_t)(q0 + r) * DK_ + c * 8);
    }
    __syncthreads();
    #pragma unroll
    for (int kf = 0; kf < 4; kf++)
        ldsm4(qh[kf], ldsm_addr(sb + (w * 16) * 144 + kf * 32, lane, 144));
    __syncthreads();   // all Q fragment reads complete before buffer 0 reuse

    auto loadTile = [&](int t, int buf) {
        const int kt = t * 64;
        #pragma unroll
        for (int i = 0; i < 4; i++) {
            int u = tid + i * 256;
            int arr = u >> 9, idx = u & 511, r = idx >> 3, c = idx & 7;
            const __half* src = (arr == 0 ? Kh : Vh) + hb + (size_t)(kt + r) * DK_ + c * 8;
            CP_ASYNC16(sb + buf * ASTAGE + arr * 9216 + r * 144 + c * 16, src);
        }
    };

    float acc[8][4];
    #pragma unroll
    for (int j = 0; j < 8; j++)
        #pragma unroll
        for (int e = 0; e < 4; e++) acc[j][e] = 0.0f;
    float ls0 = 0.0f, ls1 = 0.0f;

    loadTile(0, 0); CP_COMMIT();

    for (int t = 0; t < 32; t++) {
        CP_WAIT(0);            // tile t resident in buffer t&1
        __syncthreads();       // releases buffer (t+1)&1 (consumed at t-1)
        if (t + 1 < 32) { loadTile(t + 1, (t + 1) & 1); CP_COMMIT(); }
        const uint32_t off = sb + (t & 1) * ASTAGE;

        // ---- S = Q K^T (single product) ----
        float sc[8][4];
        #pragma unroll
        for (int j = 0; j < 8; j++)
            #pragma unroll
            for (int e = 0; e < 4; e++) sc[j][e] = 0.0f;
        #pragma unroll
        for (int kf = 0; kf < 4; kf++) {
            uint32_t kb[4][4];
            #pragma unroll
            for (int nt = 0; nt < 4; nt++)
                ldsm4(kb[nt], ldsm_addr(off + (nt * 16) * 144 + kf * 32, lane, 144));
            #pragma unroll
            for (int nt = 0; nt < 4; nt++) {
                mma_fp16(sc[2*nt],   qh[kf], kb[nt][0], kb[nt][2]);
                mma_fp16(sc[2*nt+1], qh[kf], kb[nt][1], kb[nt][3]);
            }
        }

        // ---- p = table(s) via lerp (scaled by 2^-8), accumulate row sums ----
        #pragma unroll
        for (int j = 0; j < 8; j++) {
            #pragma unroll
            for (int e = 0; e < 4; e++) {
                float tt = (sc[j][e] - TAB_LO) * TAB_INVH;
                tt = fminf(fmaxf(tt, 0.0f), 4095.0f);
                int i0 = (int)tt;
                float fr = tt - (float)i0;
                float2 tv = tabp[i0];
                sc[j][e] = fmaf(fr, tv.y, tv.x);
            }
            ls0 += sc[j][0] + sc[j][1];
            ls1 += sc[j][2] + sc[j][3];
        }

        // ---- re-pipe P to A-fragments (single fp16) ----
        uint32_t ph[4][4];
        #pragma unroll
        for (int kf = 0; kf < 4; kf++) {
            int j0 = 2 * kf;
            ph[kf][0] = packh2(sc[j0][0],   sc[j0][1]);
            ph[kf][1] = packh2(sc[j0][2],   sc[j0][3]);
            ph[kf][2] = packh2(sc[j0+1][0], sc[j0+1][1]);
            ph[kf][3] = packh2(sc[j0+1][2], sc[j0+1][3]);
        }

        // ---- acc += P V (single product) ----
        #pragma unroll
        for (int kf = 0; kf < 4; kf++) {
            uint32_t vb[4][4];
            #pragma unroll
            for (int dt = 0; dt < 4; dt++)
                ldsm4t(vb[dt], ldsm_addr(off + 9216 + (kf * 16) * 144 + dt * 32, lane, 144));
            #pragma unroll
            for (int dt = 0; dt < 4; dt++) {
                mma_fp16(acc[2*dt],   ph[kf], vb[dt][0], vb[dt][1]);
                mma_fp16(acc[2*dt+1], ph[kf], vb[dt][2], vb[dt][3]);
            }
        }
    }

    // ---- normalize (table scale cancels) and write fp16 flat [M, D] ----
    ls0 += __shfl_xor_sync(0xffffffffu, ls0, 1);
    ls0 += __shfl_xor_sync(0xffffffffu, ls0, 2);
    ls1 += __shfl_xor_sync(0xffffffffu, ls1, 1);
    ls1 += __shfl_xor_sync(0xffffffffu, ls1, 2);
    float inv0 = 1.0f / ls0, inv1 = 1.0f / ls1;
    int r0 = q0 + w * 16 + (lane >> 2);
    int bb = bh >> 4, h = bh & 15;
    #pragma unroll
    for (int j = 0; j < 8; j++) {
        int dk = j * 8 + 2 * (lane & 3);
        size_t p0 = ((size_t)(bb * S_ + r0)) * D_ + h * 64 + dk;
        size_t p1 = ((size_t)(bb * S_ + r0 + 8)) * D_ + h * 64 + dk;
        *(uint32_t*)(Oh + p0) = packh2(acc[j][0] * inv0, acc[j][1] * inv0);
        *(uint32_t*)(Oh + p1) = packh2(acc[j][2] * inv1, acc[j][3] * inv1);
    }
}

// =====================================================================
// launch
// =====================================================================
extern "C" void kernel_launch(void* const* d_in, const int* in_sizes, int n_in,
                              void* d_out, int out_size) {
    (void)in_sizes; (void)n_in; (void)out_size;
    const float* query   = (const float*)d_in[0];
    const float* key_in  = (const float*)d_in[1];
    const float* value   = (const float*)d_in[2];
    const float* w_q     = (const float*)d_in[3];
    const float* b_q     = (const float*)d_in[4];
    const float* w_k     = (const float*)d_in[5];
    const float* b_k     = (const float*)d_in[6];
    const float* w_v     = (const float*)d_in[7];
    const float* b_v     = (const float*)d_in[8];
    const float* w_o     = (const float*)d_in[9];
    const float* b_o     = (const float*)d_in[10];
    const float* centers = (const float*)d_in[11];
    const float* widths  = (const float*)d_in[12];
    const float* temp    = (const float*)d_in[13];
    float* out = (float*)d_out;

    __half *pIh, *pWh, *pQKV, *pAh;
    cudaGetSymbolAddress((void**)&pIh,  g_ih);
    cudaGetSymbolAddress((void**)&pWh,  g_wh);
    cudaGetSymbolAddress((void**)&pQKV, g_qkv);
    cudaGetSymbolAddress((void**)&pAh,  g_ah);

    cudaFuncSetAttribute(gemm_mma<0>, cudaFuncAttributeMaxDynamicSharedMemorySize, GEMM_SMEM);
    cudaFuncSetAttribute(gemm_mma<1>, cudaFuncAttributeMaxDynamicSharedMemorySize, GEMM_SMEM);
    cudaFuncSetAttribute(attn_mma, cudaFuncAttributeMaxDynamicSharedMemorySize, AT_SMEM);

    build_table<<<(TAB_N + 256) / 256, 256>>>(centers, widths, temp);

    // all conversions in one launch
    int total = 3 * NIN4 + 4 * NWW4;
    split_all<<<(total + 255) / 256, 256>>>(query, key_in, value, w_q, w_k, w_v, w_o);

    // fused QKV projections (z-dim selects; 1/sqrt(DK)=0.125 folded into Q)
    gemm_mma<1><<<dim3(D_ / 128, M_TOT / 128, 3), 256, GEMM_SMEM>>>(
        pIh, pWh, b_q, b_k, b_v, nullptr, pQKV);

    // attention (single fp16 products; writes fp16 out)
    attn_mma<<<dim3(S_ / 128, B_ * H_), 256, AT_SMEM>>>(
        pQKV, pQKV + NINel, pQKV + 2 * NINel, pAh);

    // output projection
    gemm_mma<0><<<dim3(D_ / 128, M_TOT / 128), 256, GEMM_SMEM>>>(
        pAh, pWh + 3 * NWWel, b_o, nullptr, nullptr, out, nullptr);
}

// round 14
// speedup vs baseline: 6.2190x; 1.0901x over previous
#include <cuda_runtime.h>
#include <cuda_fp16.h>
#include <cstdint>
#include <math.h>

#define B_   2
#define S_   2048
#define D_   1024
#define H_   16
#define DK_  64
#define M_TOT (B_*S_)          // 4096

#define TAB_N   4096
#define TAB_LO  (-8.0f)
#define TAB_INVH 256.0f
#define TAB_SCALE 0.00390625f   // 2^-8: keeps P within fp16 range; cancels in 1/sum

#define NINel ((size_t)M_TOT*D_)   // 4194304
#define NWWel ((size_t)D_*D_)      // 1048576

// ---- scratch (device globals) ----
__device__ float g_tab[TAB_N+1];
__device__ __half g_ih[3][NINel];     // fp16 inputs: q, k, v
__device__ __half g_wh[4][NWWel];     // fp16 weights: wq, wk, wv, wo
__device__ __half g_qkv[3][NINel];    // projected Q, K, V (head layout)
__device__ __half g_ah[NINel];        // attention output (flat [M, D])

// =====================================================================
// PTX helpers (target-independent sm_80-class instructions)
// =====================================================================
__device__ __forceinline__ uint32_t smem_u32(const void* p) {
    uint32_t a;
    asm("{ .reg .u64 t; cvta.to.shared.u64 t, %1; cvt.u32.u64 %0, t; }" : "=r"(a) : "l"(p));
    return a;
}
#define CP_ASYNC16(dst, src) asm volatile("cp.async.ca.shared.global [%0], [%1], 16;" :: "r"(dst), "l"(src))
#define CP_COMMIT() asm volatile("cp.async.commit_group;" ::: "memory")
#define CP_WAIT(n)  asm volatile("cp.async.wait_group %0;" :: "n"(n) : "memory")

__device__ __forceinline__ void ldsm4(uint32_t* r, uint32_t a) {
    asm volatile("ldmatrix.sync.aligned.m8n8.x4.shared.b16 {%0,%1,%2,%3}, [%4];"
        : "=r"(r[0]),"=r"(r[1]),"=r"(r[2]),"=r"(r[3]) : "r"(a));
}
__device__ __forceinline__ void ldsm4t(uint32_t* r, uint32_t a) {
    asm volatile("ldmatrix.sync.aligned.m8n8.x4.trans.shared.b16 {%0,%1,%2,%3}, [%4];"
        : "=r"(r[0]),"=r"(r[1]),"=r"(r[2]),"=r"(r[3]) : "r"(a));
}
__device__ __forceinline__ void mma_fp16(float* d, const uint32_t* a, uint32_t b0, uint32_t b1) {
    asm volatile("mma.sync.aligned.m16n8k16.row.col.f32.f16.f16.f32 "
        "{%0,%1,%2,%3}, {%4,%5,%6,%7}, {%8,%9}, {%0,%1,%2,%3};"
        : "+f"(d[0]),"+f"(d[1]),"+f"(d[2]),"+f"(d[3])
        : "r"(a[0]),"r"(a[1]),"r"(a[2]),"r"(a[3]), "r"(b0),"r"(b1));
}
__device__ __forceinline__ uint32_t ldsm_addr(uint32_t base, int lane, int strideB) {
    return base + (uint32_t)((lane & 15) * strideB + ((lane >> 4) << 4));
}
__device__ __forceinline__ uint32_t packh2(float a, float b) {
    __half2 h = __floats2half2_rn(a, b);
    return *reinterpret_cast<uint32_t*>(&h);
}

// =====================================================================
// 0) batched fp32 -> fp16 conversion: 3 inputs + 4 weights
// =====================================================================
#define NIN4 (M_TOT*D_/4)   // 1048576
#define NWW4 (D_*D_/4)      // 262144

__global__ void split_all(const float* __restrict__ q, const float* __restrict__ k,
                          const float* __restrict__ v, const float* __restrict__ wq,
                          const float* __restrict__ wk, const float* __restrict__ wv,
                          const float* __restrict__ wo) {
    int i = blockIdx.x * blockDim.x + threadIdx.x;
    const float* src; __half* dst; size_t off;
    if (i < 3 * NIN4) {
        int seg = i / NIN4; off = (size_t)(i - seg * NIN4);
        src = seg == 0 ? q : seg == 1 ? k : v;
        dst = g_ih[seg];
    } else {
        int j = i - 3 * NIN4;
        if (j >= 4 * NWW4) return;
        int seg = j / NWW4; off = (size_t)(j - seg * NWW4);
        src = seg == 0 ? wq : seg == 1 ? wk : seg == 2 ? wv : wo;
        dst = g_wh[seg];
    }
    float4 vv = ((const float4*)src)[off];
    *(uint2*)(dst + 4 * off) = make_uint2(packh2(vv.x, vv.y), packh2(vv.z, vv.w));
}

// =====================================================================
// 1) table: g(s) = exp( sum_i gauss_i(s) / (3 T) ) * 2^-8
// =====================================================================
__global__ void build_table(const float* __restrict__ centers,
                            const float* __restrict__ widths,
                            const float* __restrict__ temp) {
    int i = blockIdx.x * blockDim.x + threadIdx.x;
    if (i > TAB_N) return;
    float s = TAB_LO + (float)i * (1.0f / TAB_INVH);
    float acc = 0.0f;
    #pragma unroll 1
    for (int j = 0; j < H_*3; j++) {
        float c = centers[j];
        float w = widths[j];
        float d = s - c;
        acc += expf(-(d*d) / (2.0f * w * w));
    }
    g_tab[i] = expf(acc / (3.0f * temp[0])) * TAB_SCALE;
}

// =====================================================================
// 2) HMMA GEMM: C = A @ W^T + bias   (single fp16 product)
//    128x128 tile, k-chunk 32, 8 warps (4m x 2n), 2-stage cp.async.
//    MODE 0: O-projection, fp32 flat store, grid (8,32).
//    MODE 1: fused QKV, grid (8,32,3); z selects seg; fp16 head-layout out.
// =====================================================================
#define GK 32
#define GSTRIDE 80              // bytes per smem row (32+8 fp16)
#define GBUF 10240              // one array: 128 rows * 80B
#define GSTAGE (2*GBUF)         // 20480 (A, W)
#define GEMM_SMEM (2*GSTAGE)    // 40960

template<int MODE>
__global__ void __launch_bounds__(256)
gemm_mma(const __half* __restrict__ A0, const __half* __restrict__ W0,
         const float* __restrict__ bq, const float* __restrict__ bk,
         const float* __restrict__ bv,
         float* __restrict__ C, __half* __restrict__ Ch) {
    extern __shared__ char smem[];
    const uint32_t sb = smem_u32(smem);
    const int tid = threadIdx.x, w = tid >> 5, lane = tid & 31;
    const int m0 = blockIdx.y * 128, n0 = blockIdx.x * 128;
    const int wm = (w >> 1) * 32, wn = (w & 1) * 64;

    const __half* A = A0;
    const __half* W = W0;
    const float* bias = bq;
    __half* Chz = Ch;
    float scale = 1.0f;
    if (MODE == 1) {
        int z = blockIdx.z;
        A = A0 + (size_t)z * NINel;
        W = W0 + (size_t)z * NWWel;
        bias = z == 0 ? bq : (z == 1 ? bk : bv);
        Chz = Ch + (size_t)z * NINel;
        scale = (z == 0) ? 0.125f : 1.0f;
    }

    float acc[2][8][4];
    #pragma unroll
    for (int a = 0; a < 2; a++)
        #pragma unroll
        for (int b = 0; b < 8; b++)
            #pragma unroll
            for (int c = 0; c < 4; c++) acc[a][b][c] = 0.0f;

    auto loadChunk = [&](int c, int buf) {
        const uint32_t off = sb + buf * GSTAGE;
        const int k0 = c * GK;
        #pragma unroll
        for (int i = 0; i < 4; i++) {
            int u = tid + i * 256;
            int arr = u >> 9, idx = u & 511;
            int r = idx >> 2, cc = idx & 3;
            const __half* src = arr == 0 ? A + (size_t)(m0 + r) * D_ + k0 + cc * 8
                                         : W + (size_t)(n0 + r) * D_ + k0 + cc * 8;
            CP_ASYNC16(off + arr * GBUF + r * GSTRIDE + cc * 16, src);
        }
    };
    auto compute = [&](int buf) {
        const uint32_t off = sb + buf * GSTAGE;
        uint32_t Ah[2][2][4];
        #pragma unroll
        for (int mi = 0; mi < 2; mi++)
            #pragma unroll
            for (int kf = 0; kf < 2; kf++)
                ldsm4(Ah[mi][kf], ldsm_addr(off + (wm + mi * 16) * GSTRIDE + kf * 32, lane, GSTRIDE));
        #pragma unroll
        for (int kf = 0; kf < 2; kf++) {
            uint32_t Bh[4][4];
            #pragma unroll
            for (int nt = 0; nt < 4; nt++)
                ldsm4(Bh[nt], ldsm_addr(off + GBUF + (wn + nt * 16) * GSTRIDE + kf * 32, lane, GSTRIDE));
            #pragma unroll
            for (int mi = 0; mi < 2; mi++)
                #pragma unroll
                for (int nt = 0; nt < 4; nt++) {
                    mma_fp16(acc[mi][2*nt],   Ah[mi][kf], Bh[nt][0], Bh[nt][2]);
                    mma_fp16(acc[mi][2*nt+1], Ah[mi][kf], Bh[nt][1], Bh[nt][3]);
                }
        }
    };

    loadChunk(0, 0); CP_COMMIT();
    for (int c = 0; c < 32; c++) {
        CP_WAIT(0);            // chunk c resident in buffer c&1
        __syncthreads();       // also releases buffer (c+1)&1 (computed at c-1)
        if (c + 1 < 32) { loadChunk(c + 1, (c + 1) & 1); CP_COMMIT(); }
        compute(c & 1);        // overlaps with in-flight load of chunk c+1
    }

    // epilogue
    #pragma unroll
    for (int mi = 0; mi < 2; mi++) {
        int r0 = m0 + wm + mi * 16 + (lane >> 2);
        #pragma unroll
        for (int ni = 0; ni < 8; ni++) {
            int col = n0 + wn + ni * 8 + 2 * (lane & 3);
            float b0v = __ldg(bias + col), b1v = __ldg(bias + col + 1);
            #pragma unroll
            for (int rr = 0; rr < 2; rr++) {
                int row = r0 + rr * 8;
                float v0 = (acc[mi][ni][2*rr]   + b0v) * scale;
                float v1 = (acc[mi][ni][2*rr+1] + b1v) * scale;
                if (MODE == 0) {
                    *(float2*)(C + (size_t)row * D_ + col) = make_float2(v0, v1);
                } else {
                    int bb = row >> 11, s = row & 2047, h = col >> 6, dk = col & 63;
                    size_t p = ((size_t)((bb * H_ + h) * S_ + s)) * DK_ + dk;
                    *(uint32_t*)(Chz + p) = packh2(v0, v1);
                }
            }
        }
    }
}

// =====================================================================
// 3) HMMA flash attention, single fp16, 32 q-rows PER WARP (256/CTA).
//    K/V fragments loaded once per warp feed 2x the MMAs (ldsm:MMA 1:4).
//    grid (S/256, B*H) = (8, 32); 8 warps; k-tile 64; 2-stage pipeline.
//    stage buf: Kh@0 Vh@9216 (64 rows x 144B). Q staged across both bufs.
// =====================================================================
#define ASTAGE 18432
#define AT_SMEM (2*ASTAGE + TAB_N*8)   // 36864 + 32768 = 69632

__global__ void __launch_bounds__(256, 1)
attn_mma(const __half* __restrict__ Qh, const __half* __restrict__ Kh,
         const __half* __restrict__ Vh, __half* __restrict__ Oh) {
    extern __shared__ char smem[];
    const uint32_t sb = smem_u32(smem);
    float2* tabp = (float2*)(smem + 2 * ASTAGE);
    const int tid = threadIdx.x, w = tid >> 5, lane = tid & 31;
    const int bh = blockIdx.y, q0 = blockIdx.x * 256;
    const size_t hb = (size_t)bh * S_ * DK_;

    for (int i = tid; i < TAB_N; i += 256) {
        float a = g_tab[i];
        tabp[i] = make_float2(a, g_tab[i + 1] - a);
    }

    // ---- stage all 256 Q rows across both stage buffers (36864B), load frags ----
    uint32_t qh[2][4][4];
    for (int u = tid; u < 2048; u += 256) {
        int r = u >> 3, c = u & 7;
        *(uint4*)(smem + r * 144 + c * 16) = *(const uint4*)(Qh + hb + (size_t)(q0 + r) * DK_ + c * 8);
    }
    __syncthreads();
    #pragma unroll
    for (int mi = 0; mi < 2; mi++)
        #pragma unroll
        for (int kf = 0; kf < 4; kf++)
            ldsm4(qh[mi][kf], ldsm_addr(sb + (w * 32 + mi * 16) * 144 + kf * 32, lane, 144));
    __syncthreads();   // all Q fragment reads complete before buffers are reused

    auto loadTile = [&](int t, int buf) {
        const int kt = t * 64;
        #pragma unroll
        for (int i = 0; i < 4; i++) {
            int u = tid + i * 256;
            int arr = u >> 9, idx = u & 511, r = idx >> 3, c = idx & 7;
            const __half* src = (arr == 0 ? Kh : Vh) + hb + (size_t)(kt + r) * DK_ + c * 8;
            CP_ASYNC16(sb + buf * ASTAGE + arr * 9216 + r * 144 + c * 16, src);
        }
    };

    float acc[2][8][4];
    #pragma unroll
    for (int mi = 0; mi < 2; mi++)
        #pragma unroll
        for (int j = 0; j < 8; j++)
            #pragma unroll
            for (int e = 0; e < 4; e++) acc[mi][j][e] = 0.0f;
    float ls[2][2] = {{0.0f, 0.0f}, {0.0f, 0.0f}};

    loadTile(0, 0); CP_COMMIT();

    for (int t = 0; t < 32; t++) {
        CP_WAIT(0);            // tile t resident in buffer t&1
        __syncthreads();       // releases buffer (t+1)&1 (consumed at t-1)
        if (t + 1 < 32) { loadTile(t + 1, (t + 1) & 1); CP_COMMIT(); }
        const uint32_t off = sb + (t & 1) * ASTAGE;

        // ---- S = Q K^T: K frags loaded ONCE per warp serve both mi ----
        float sc[2][8][4];
        #pragma unroll
        for (int mi = 0; mi < 2; mi++)
            #pragma unroll
            for (int j = 0; j < 8; j++)
                #pragma unroll
                for (int e = 0; e < 4; e++) sc[mi][j][e] = 0.0f;
        #pragma unroll
        for (int kf = 0; kf < 4; kf++) {
            uint32_t kb[4][4];
            #pragma unroll
            for (int nt = 0; nt < 4; nt++)
                ldsm4(kb[nt], ldsm_addr(off + (nt * 16) * 144 + kf * 32, lane, 144));
            #pragma unroll
            for (int mi = 0; mi < 2; mi++)
                #pragma unroll
                for (int nt = 0; nt < 4; nt++) {
                    mma_fp16(sc[mi][2*nt],   qh[mi][kf], kb[nt][0], kb[nt][2]);
                    mma_fp16(sc[mi][2*nt+1], qh[mi][kf], kb[nt][1], kb[nt][3]);
                }
        }

        // ---- p = table(s) via lerp (scaled 2^-8), row sums ----
        #pragma unroll
        for (int mi = 0; mi < 2; mi++)
            #pragma unroll
            for (int j = 0; j < 8; j++) {
                #pragma unroll
                for (int e = 0; e < 4; e++) {
                    float tt = fmaf(sc[mi][j][e], TAB_INVH, 2048.0f);
                    tt = fminf(fmaxf(tt, 0.0f), 4095.0f);
                    int i0 = (int)tt;
                    float fr = tt - (float)i0;
                    float2 tv = tabp[i0];
                    sc[mi][j][e] = fmaf(fr, tv.y, tv.x);
                }
                ls[mi][0] += sc[mi][j][0] + sc[mi][j][1];
                ls[mi][1] += sc[mi][j][2] + sc[mi][j][3];
            }

        // ---- re-pipe P to A-fragments (single fp16) ----
        uint32_t ph[2][4][4];
        #pragma unroll
        for (int mi = 0; mi < 2; mi++)
            #pragma unroll
            for (int kf = 0; kf < 4; kf++) {
                int j0 = 2 * kf;
                ph[mi][kf][0] = packh2(sc[mi][j0][0],   sc[mi][j0][1]);
                ph[mi][kf][1] = packh2(sc[mi][j0][2],   sc[mi][j0][3]);
                ph[mi][kf][2] = packh2(sc[mi][j0+1][0], sc[mi][j0+1][1]);
                ph[mi][kf][3] = packh2(sc[mi][j0+1][2], sc[mi][j0+1][3]);
            }

        // ---- acc += P V: V frags loaded ONCE per warp serve both mi ----
        #pragma unroll
        for (int kf = 0; kf < 4; kf++) {
            uint32_t vb[4][4];
            #pragma unroll
            for (int dt = 0; dt < 4; dt++)
                ldsm4t(vb[dt], ldsm_addr(off + 9216 + (kf * 16) * 144 + dt * 32, lane, 144));
            #pragma unroll
            for (int mi = 0; mi < 2; mi++)
                #pragma unroll
                for (int dt = 0; dt < 4; dt++) {
                    mma_fp16(acc[mi][2*dt],   ph[mi][kf], vb[dt][0], vb[dt][1]);
                    mma_fp16(acc[mi][2*dt+1], ph[mi][kf], vb[dt][2], vb[dt][3]);
                }
        }
    }

    // ---- normalize (table scale cancels) and write fp16 flat [M, D] ----
    int bb = bh >> 4, h = bh & 15;
    #pragma unroll
    for (int mi = 0; mi < 2; mi++) {
        float l0 = ls[mi][0], l1 = ls[mi][1];
        l0 += __shfl_xor_sync(0xffffffffu, l0, 1);
        l0 += __shfl_xor_sync(0xffffffffu, l0, 2);
        l1 += __shfl_xor_sync(0xffffffffu, l1, 1);
        l1 += __shfl_xor_sync(0xffffffffu, l1, 2);
        float inv0 = 1.0f / l0, inv1 = 1.0f / l1;
        int r0 = q0 + w * 32 + mi * 16 + (lane >> 2);
        #pragma unroll
        for (int j = 0; j < 8; j++) {
            int dk = j * 8 + 2 * (lane & 3);
            size_t p0 = ((size_t)(bb * S_ + r0)) * D_ + h * 64 + dk;
            size_t p1 = ((size_t)(bb * S_ + r0 + 8)) * D_ + h * 64 + dk;
            *(uint32_t*)(Oh + p0) = packh2(acc[mi][j][0] * inv0, acc[mi][j][1] * inv0);
            *(uint32_t*)(Oh + p1) = packh2(acc[mi][j][2] * inv1, acc[mi][j][3] * inv1);
        }
    }
}

// =====================================================================
// launch
// =====================================================================
extern "C" void kernel_launch(void* const* d_in, const int* in_sizes, int n_in,
                              void* d_out, int out_size) {
    (void)in_sizes; (void)n_in; (void)out_size;
    const float* query   = (const float*)d_in[0];
    const float* key_in  = (const float*)d_in[1];
    const float* value   = (const float*)d_in[2];
    const float* w_q     = (const float*)d_in[3];
    const float* b_q     = (const float*)d_in[4];
    const float* w_k     = (const float*)d_in[5];
    const float* b_k     = (const float*)d_in[6];
    const float* w_v     = (const float*)d_in[7];
    const float* b_v     = (const float*)d_in[8];
    const float* w_o     = (const float*)d_in[9];
    const float* b_o     = (const float*)d_in[10];
    const float* centers = (const float*)d_in[11];
    const float* widths  = (const float*)d_in[12];
    const float* temp    = (const float*)d_in[13];
    float* out = (float*)d_out;

    __half *pIh, *pWh, *pQKV, *pAh;
    cudaGetSymbolAddress((void**)&pIh,  g_ih);
    cudaGetSymbolAddress((void**)&pWh,  g_wh);
    cudaGetSymbolAddress((void**)&pQKV, g_qkv);
    cudaGetSymbolAddress((void**)&pAh,  g_ah);

    cudaFuncSetAttribute(gemm_mma<0>, cudaFuncAttributeMaxDynamicSharedMemorySize, GEMM_SMEM);
    cudaFuncSetAttribute(gemm_mma<1>, cudaFuncAttributeMaxDynamicSharedMemorySize, GEMM_SMEM);
    cudaFuncSetAttribute(attn_mma, cudaFuncAttributeMaxDynamicSharedMemorySize, AT_SMEM);

    build_table<<<(TAB_N + 256) / 256, 256>>>(centers, widths, temp);

    // all conversions in one launch
    int total = 3 * NIN4 + 4 * NWW4;
    split_all<<<(total + 255) / 256, 256>>>(query, key_in, value, w_q, w_k, w_v, w_o);

    // fused QKV projections (z-dim selects; 1/sqrt(DK)=0.125 folded into Q)
    gemm_mma<1><<<dim3(D_ / 128, M_TOT / 128, 3), 256, GEMM_SMEM>>>(
        pIh, pWh, b_q, b_k, b_v, nullptr, pQKV);

    // attention (32 q-rows/warp; single fp16 products)
    attn_mma<<<dim3(S_ / 256, B_ * H_), 256, AT_SMEM>>>(
        pQKV, pQKV + NINel, pQKV + 2 * NINel, pAh);

    // output projection
    gemm_mma<0><<<dim3(D_ / 128, M_TOT / 128), 256, GEMM_SMEM>>>(
        pAh, pWh + 3 * NWWel, b_o, nullptr, nullptr, out, nullptr);
}